// round 1
// baseline (speedup 1.0000x reference)
#include <cuda_runtime.h>

#define SEQ_L 2048
#define DIM 1024
#define NHEAD 16
#define DHEAD 64
#define BATCH 2

// Scratch (allocation-free): Q/K/V in [B,H,L,DH], O in [B,L,D]
__device__ float g_Q[BATCH * NHEAD * SEQ_L * DHEAD];
__device__ float g_K[BATCH * NHEAD * SEQ_L * DHEAD];
__device__ float g_V[BATCH * NHEAD * SEQ_L * DHEAD];
__device__ float g_O[BATCH * SEQ_L * DIM];

// ---------------------------------------------------------------------------
// Tiled SGEMM: out = X[M,K] @ W[K,N] + bias[N]
// 128x128 tile, BK=8, 256 threads, 8x8 register micro-tile (split 4+4).
// remap=1: scatter into [B,H,L,DH] layout; remap=0: row-major [M,N].
// ---------------------------------------------------------------------------
__global__ __launch_bounds__(256) void gemm_bias(
    const float* __restrict__ X, const float* __restrict__ W,
    const float* __restrict__ bias, float* __restrict__ out,
    int M, int Kdim, int N, int remap)
{
    __shared__ float As[8][128];   // transposed A tile: As[k][m]
    __shared__ float Bs[8][128];

    const int tid = threadIdx.x;
    const int bm = blockIdx.y * 128;
    const int bn = blockIdx.x * 128;
    const int tx = tid & 15;
    const int ty = tid >> 4;

    const int arow = tid >> 1;          // 0..127
    const int acol = (tid & 1) << 2;    // 0 or 4
    const int brow = tid >> 5;          // 0..7
    const int bcol = (tid & 31) << 2;   // 0..124

    const float* Xp = X + (size_t)(bm + arow) * Kdim + acol;
    const float* Wp = W + (size_t)brow * N + bn + bcol;

    float acc[8][8];
#pragma unroll
    for (int i = 0; i < 8; i++)
#pragma unroll
        for (int j = 0; j < 8; j++) acc[i][j] = 0.f;

    for (int k0 = 0; k0 < Kdim; k0 += 8) {
        float4 a = *(const float4*)Xp;
        float4 bb = *(const float4*)Wp;
        As[acol + 0][arow] = a.x;
        As[acol + 1][arow] = a.y;
        As[acol + 2][arow] = a.z;
        As[acol + 3][arow] = a.w;
        *(float4*)&Bs[brow][bcol] = bb;
        __syncthreads();
#pragma unroll
        for (int kk = 0; kk < 8; kk++) {
            float ra[8], rb[8];
            *(float4*)&ra[0] = *(const float4*)&As[kk][ty * 4];
            *(float4*)&ra[4] = *(const float4*)&As[kk][64 + ty * 4];
            *(float4*)&rb[0] = *(const float4*)&Bs[kk][tx * 4];
            *(float4*)&rb[4] = *(const float4*)&Bs[kk][64 + tx * 4];
#pragma unroll
            for (int i = 0; i < 8; i++)
#pragma unroll
                for (int j = 0; j < 8; j++) acc[i][j] += ra[i] * rb[j];
        }
        __syncthreads();
        Xp += 8;
        Wp += (size_t)8 * N;
    }

#pragma unroll
    for (int i = 0; i < 8; i++) {
        int row = bm + ((i < 4) ? (ty * 4 + i) : (64 + ty * 4 + i - 4));
#pragma unroll
        for (int j = 0; j < 8; j++) {
            int col = bn + ((j < 4) ? (tx * 4 + j) : (64 + tx * 4 + j - 4));
            float val = acc[i][j] + bias[col];
            if (remap) {
                // row -> (b, l);  col -> (h, dh);  out layout [B,H,L,DH]
                int b = row >> 11;           // L = 2048 = 2^11
                int l = row & (SEQ_L - 1);
                int h = col >> 6;            // DH = 64
                int dh = col & 63;
                out[((((size_t)b * NHEAD + h) * SEQ_L + l) << 6) + dh] = val;
            } else {
                out[(size_t)row * N + col] = val;
            }
        }
    }
}

// ---------------------------------------------------------------------------
// Causal flash attention, fp32 SIMT.
// Grid: (L/64, H, B). Block: 256 threads = 64 rows x 4-thread teams.
// Each team thread owns 16 of the 64 head dims. Online softmax in chunks of 16.
// ---------------------------------------------------------------------------
__global__ __launch_bounds__(256) void attn_kernel(
    const float* __restrict__ Q, const float* __restrict__ K,
    const float* __restrict__ V, float* __restrict__ O)
{
    __shared__ float sQ[64][64];
    __shared__ float sK[64][64];
    __shared__ float sV[64][64];

    const int qb = blockIdx.x;
    const int h = blockIdx.y;
    const int b = blockIdx.z;
    const int tid = threadIdx.x;
    const int r = tid >> 2;   // q-row within tile 0..63
    const int t = tid & 3;    // team lane: owns dims [t*16, t*16+16)

    const size_t headOff = (size_t)(b * NHEAD + h) * SEQ_L * DHEAD;
    const float* Qb = Q + headOff + (size_t)qb * 64 * DHEAD;

    // Load Q tile (64x64 floats, 4 float4 per thread)
    for (int i = tid; i < 64 * 16; i += 256) {
        int row = i >> 4;
        int c4 = (i & 15) << 2;
        *(float4*)&sQ[row][c4] = *(const float4*)(Qb + row * DHEAD + c4);
    }
    __syncthreads();

    float qreg[16];
#pragma unroll
    for (int d = 0; d < 16; d++) qreg[d] = sQ[r][t * 16 + d];

    float acc[16];
#pragma unroll
    for (int d = 0; d < 16; d++) acc[d] = 0.f;
    float m = -3.0e38f;
    float l = 0.f;
    const int qg = qb * 64 + r;   // global q index

    for (int kb = 0; kb <= qb; kb++) {
        __syncthreads();   // protect sK/sV (and sQ on first iter) from overwrite
        const float* Kt = K + headOff + (size_t)kb * 64 * DHEAD;
        const float* Vt = V + headOff + (size_t)kb * 64 * DHEAD;
        for (int i = tid; i < 64 * 16; i += 256) {
            int row = i >> 4;
            int c4 = (i & 15) << 2;
            *(float4*)&sK[row][c4] = *(const float4*)(Kt + row * DHEAD + c4);
            *(float4*)&sV[row][c4] = *(const float4*)(Vt + row * DHEAD + c4);
        }
        __syncthreads();

        const bool diag = (kb == qb);
        const int kb64 = kb * 64;

        for (int jc = 0; jc < 64; jc += 16) {
            float s[16];
#pragma unroll
            for (int jj = 0; jj < 16; jj++) {
                int j = jc + jj;
                const float4* kr = (const float4*)&sK[j][t * 16];
                float4 k0 = kr[0], k1 = kr[1], k2 = kr[2], k3 = kr[3];
                float p = qreg[0] * k0.x + qreg[1] * k0.y + qreg[2] * k0.z + qreg[3] * k0.w
                        + qreg[4] * k1.x + qreg[5] * k1.y + qreg[6] * k1.z + qreg[7] * k1.w
                        + qreg[8] * k2.x + qreg[9] * k2.y + qreg[10] * k2.z + qreg[11] * k2.w
                        + qreg[12] * k3.x + qreg[13] * k3.y + qreg[14] * k3.z + qreg[15] * k3.w;
                p += __shfl_xor_sync(0xffffffffu, p, 1);
                p += __shfl_xor_sync(0xffffffffu, p, 2);
                p *= 0.125f;   // 1/sqrt(DH)
                if (diag && (kb64 + j > qg)) p = -1e30f;
                s[jj] = p;
            }
            float mc = s[0];
#pragma unroll
            for (int jj = 1; jj < 16; jj++) mc = fmaxf(mc, s[jj]);
            float mnew = fmaxf(m, mc);
            float corr = __expf(m - mnew);
            l *= corr;
#pragma unroll
            for (int d = 0; d < 16; d++) acc[d] *= corr;
#pragma unroll
            for (int jj = 0; jj < 16; jj++) {
                int j = jc + jj;
                float pj = __expf(s[jj] - mnew);
                if (diag && (kb64 + j > qg)) pj = 0.f;  // bulletproof vs all-masked chunk
                l += pj;
                const float4* vr = (const float4*)&sV[j][t * 16];
                float4 v0 = vr[0], v1 = vr[1], v2 = vr[2], v3 = vr[3];
                acc[0] += pj * v0.x;  acc[1] += pj * v0.y;
                acc[2] += pj * v0.z;  acc[3] += pj * v0.w;
                acc[4] += pj * v1.x;  acc[5] += pj * v1.y;
                acc[6] += pj * v1.z;  acc[7] += pj * v1.w;
                acc[8] += pj * v2.x;  acc[9] += pj * v2.y;
                acc[10] += pj * v2.z; acc[11] += pj * v2.w;
                acc[12] += pj * v3.x; acc[13] += pj * v3.y;
                acc[14] += pj * v3.z; acc[15] += pj * v3.w;
            }
            m = mnew;
        }
    }

    float inv = 1.f / l;
    // O layout [B, L, D]: row (b, qg), cols h*64 + t*16 ..
    float* Op = O + ((size_t)(b * SEQ_L + qg) * DIM) + h * DHEAD + t * 16;
#pragma unroll
    for (int d = 0; d < 16; d++) Op[d] = acc[d] * inv;
}

// ---------------------------------------------------------------------------
extern "C" void kernel_launch(void* const* d_in, const int* in_sizes, int n_in,
                              void* d_out, int out_size)
{
    const float* q  = (const float*)d_in[0];
    const float* k  = (const float*)d_in[1];
    const float* v  = (const float*)d_in[2];
    // d_in[3] = mask (causal triu) — applied analytically, not read
    const float* Wq = (const float*)d_in[4];
    const float* bq = (const float*)d_in[5];
    const float* Wk = (const float*)d_in[6];
    const float* bk = (const float*)d_in[7];
    const float* Wv = (const float*)d_in[8];
    const float* bv = (const float*)d_in[9];
    const float* Wo = (const float*)d_in[10];
    const float* bo = (const float*)d_in[11];

    float *gq, *gk, *gv, *go;
    cudaGetSymbolAddress((void**)&gq, g_Q);
    cudaGetSymbolAddress((void**)&gk, g_K);
    cudaGetSymbolAddress((void**)&gv, g_V);
    cudaGetSymbolAddress((void**)&go, g_O);

    const int M = BATCH * SEQ_L;   // 4096
    dim3 ggrid(DIM / 128, M / 128);   // (8, 32)

    gemm_bias<<<ggrid, 256>>>(q, Wq, bq, gq, M, DIM, DIM, 1);
    gemm_bias<<<ggrid, 256>>>(k, Wk, bk, gk, M, DIM, DIM, 1);
    gemm_bias<<<ggrid, 256>>>(v, Wv, bv, gv, M, DIM, DIM, 1);

    attn_kernel<<<dim3(SEQ_L / 64, NHEAD, BATCH), 256>>>(gq, gk, gv, go);

    gemm_bias<<<ggrid, 256>>>(go, Wo, bo, (float*)d_out, M, DIM, DIM, 0);
}

// round 2
// speedup vs baseline: 1.0035x; 1.0035x over previous
#include <cuda_runtime.h>

#define SEQ_L 2048
#define DIM 1024
#define NHEAD 16
#define DHEAD 64
#define BATCH 2

// Scratch (allocation-free): Q/K/V in [B,H,L,DH], O in [B,L,D]
__device__ float g_Q[BATCH * NHEAD * SEQ_L * DHEAD];
__device__ float g_K[BATCH * NHEAD * SEQ_L * DHEAD];
__device__ float g_V[BATCH * NHEAD * SEQ_L * DHEAD];
__device__ float g_O[BATCH * SEQ_L * DIM];

// ---------------------------------------------------------------------------
// Tiled SGEMM: out = X[M,K] @ W[K,N] + bias[N]
// 128x128 tile, BK=8, 256 threads, 8x8 register micro-tile (split 4+4).
// remap=1: scatter into [B,H,L,DH] layout; remap=0: row-major [M,N].
// ---------------------------------------------------------------------------
__global__ __launch_bounds__(256) void gemm_bias(
    const float* __restrict__ X, const float* __restrict__ W,
    const float* __restrict__ bias, float* __restrict__ out,
    int M, int Kdim, int N, int remap)
{
    __shared__ float As[8][128];   // transposed A tile: As[k][m]
    __shared__ float Bs[8][128];

    const int tid = threadIdx.x;
    const int bm = blockIdx.y * 128;
    const int bn = blockIdx.x * 128;
    const int tx = tid & 15;
    const int ty = tid >> 4;

    const int arow = tid >> 1;          // 0..127
    const int acol = (tid & 1) << 2;    // 0 or 4
    const int brow = tid >> 5;          // 0..7
    const int bcol = (tid & 31) << 2;   // 0..124

    const float* Xp = X + (size_t)(bm + arow) * Kdim + acol;
    const float* Wp = W + (size_t)brow * N + bn + bcol;

    float acc[8][8];
#pragma unroll
    for (int i = 0; i < 8; i++)
#pragma unroll
        for (int j = 0; j < 8; j++) acc[i][j] = 0.f;

    for (int k0 = 0; k0 < Kdim; k0 += 8) {
        float4 a = *(const float4*)Xp;
        float4 bb = *(const float4*)Wp;
        As[acol + 0][arow] = a.x;
        As[acol + 1][arow] = a.y;
        As[acol + 2][arow] = a.z;
        As[acol + 3][arow] = a.w;
        *(float4*)&Bs[brow][bcol] = bb;
        __syncthreads();
#pragma unroll
        for (int kk = 0; kk < 8; kk++) {
            float ra[8], rb[8];
            *(float4*)&ra[0] = *(const float4*)&As[kk][ty * 4];
            *(float4*)&ra[4] = *(const float4*)&As[kk][64 + ty * 4];
            *(float4*)&rb[0] = *(const float4*)&Bs[kk][tx * 4];
            *(float4*)&rb[4] = *(const float4*)&Bs[kk][64 + tx * 4];
#pragma unroll
            for (int i = 0; i < 8; i++)
#pragma unroll
                for (int j = 0; j < 8; j++) acc[i][j] += ra[i] * rb[j];
        }
        __syncthreads();
        Xp += 8;
        Wp += (size_t)8 * N;
    }

#pragma unroll
    for (int i = 0; i < 8; i++) {
        int row = bm + ((i < 4) ? (ty * 4 + i) : (64 + ty * 4 + i - 4));
#pragma unroll
        for (int j = 0; j < 8; j++) {
            int col = bn + ((j < 4) ? (tx * 4 + j) : (64 + tx * 4 + j - 4));
            float val = acc[i][j] + bias[col];
            if (remap) {
                // row -> (b, l);  col -> (h, dh);  out layout [B,H,L,DH]
                int b = row >> 11;           // L = 2048 = 2^11
                int l = row & (SEQ_L - 1);
                int h = col >> 6;            // DH = 64
                int dh = col & 63;
                out[((((size_t)b * NHEAD + h) * SEQ_L + l) << 6) + dh] = val;
            } else {
                out[(size_t)row * N + col] = val;
            }
        }
    }
}

// ---------------------------------------------------------------------------
// Causal flash attention, fp32 SIMT.
// Grid: (L/64, H, B). Block: 256 threads = 64 rows x 4-thread teams.
// Each team thread owns 16 of the 64 head dims. Online softmax in chunks of 16.
// ---------------------------------------------------------------------------
__global__ __launch_bounds__(256) void attn_kernel(
    const float* __restrict__ Q, const float* __restrict__ K,
    const float* __restrict__ V, float* __restrict__ O)
{
    __shared__ float sQ[64][64];
    __shared__ float sK[64][64];
    __shared__ float sV[64][64];

    const int qb = blockIdx.x;
    const int h = blockIdx.y;
    const int b = blockIdx.z;
    const int tid = threadIdx.x;
    const int r = tid >> 2;   // q-row within tile 0..63
    const int t = tid & 3;    // team lane: owns dims [t*16, t*16+16)

    const size_t headOff = (size_t)(b * NHEAD + h) * SEQ_L * DHEAD;
    const float* Qb = Q + headOff + (size_t)qb * 64 * DHEAD;

    // Load Q tile (64x64 floats, 4 float4 per thread)
    for (int i = tid; i < 64 * 16; i += 256) {
        int row = i >> 4;
        int c4 = (i & 15) << 2;
        *(float4*)&sQ[row][c4] = *(const float4*)(Qb + row * DHEAD + c4);
    }
    __syncthreads();

    float qreg[16];
#pragma unroll
    for (int d = 0; d < 16; d++) qreg[d] = sQ[r][t * 16 + d];

    float acc[16];
#pragma unroll
    for (int d = 0; d < 16; d++) acc[d] = 0.f;
    float m = -3.0e38f;
    float l = 0.f;
    const int qg = qb * 64 + r;   // global q index

    for (int kb = 0; kb <= qb; kb++) {
        __syncthreads();   // protect sK/sV (and sQ on first iter) from overwrite
        const float* Kt = K + headOff + (size_t)kb * 64 * DHEAD;
        const float* Vt = V + headOff + (size_t)kb * 64 * DHEAD;
        for (int i = tid; i < 64 * 16; i += 256) {
            int row = i >> 4;
            int c4 = (i & 15) << 2;
            *(float4*)&sK[row][c4] = *(const float4*)(Kt + row * DHEAD + c4);
            *(float4*)&sV[row][c4] = *(const float4*)(Vt + row * DHEAD + c4);
        }
        __syncthreads();

        const bool diag = (kb == qb);
        const int kb64 = kb * 64;

        for (int jc = 0; jc < 64; jc += 16) {
            float s[16];
#pragma unroll
            for (int jj = 0; jj < 16; jj++) {
                int j = jc + jj;
                const float4* kr = (const float4*)&sK[j][t * 16];
                float4 k0 = kr[0], k1 = kr[1], k2 = kr[2], k3 = kr[3];
                float p = qreg[0] * k0.x + qreg[1] * k0.y + qreg[2] * k0.z + qreg[3] * k0.w
                        + qreg[4] * k1.x + qreg[5] * k1.y + qreg[6] * k1.z + qreg[7] * k1.w
                        + qreg[8] * k2.x + qreg[9] * k2.y + qreg[10] * k2.z + qreg[11] * k2.w
                        + qreg[12] * k3.x + qreg[13] * k3.y + qreg[14] * k3.z + qreg[15] * k3.w;
                p += __shfl_xor_sync(0xffffffffu, p, 1);
                p += __shfl_xor_sync(0xffffffffu, p, 2);
                p *= 0.125f;   // 1/sqrt(DH)
                if (diag && (kb64 + j > qg)) p = -1e30f;
                s[jj] = p;
            }
            float mc = s[0];
#pragma unroll
            for (int jj = 1; jj < 16; jj++) mc = fmaxf(mc, s[jj]);
            float mnew = fmaxf(m, mc);
            float corr = __expf(m - mnew);
            l *= corr;
#pragma unroll
            for (int d = 0; d < 16; d++) acc[d] *= corr;
#pragma unroll
            for (int jj = 0; jj < 16; jj++) {
                int j = jc + jj;
                float pj = __expf(s[jj] - mnew);
                if (diag && (kb64 + j > qg)) pj = 0.f;  // bulletproof vs all-masked chunk
                l += pj;
                const float4* vr = (const float4*)&sV[j][t * 16];
                float4 v0 = vr[0], v1 = vr[1], v2 = vr[2], v3 = vr[3];
                acc[0] += pj * v0.x;  acc[1] += pj * v0.y;
                acc[2] += pj * v0.z;  acc[3] += pj * v0.w;
                acc[4] += pj * v1.x;  acc[5] += pj * v1.y;
                acc[6] += pj * v1.z;  acc[7] += pj * v1.w;
                acc[8] += pj * v2.x;  acc[9] += pj * v2.y;
                acc[10] += pj * v2.z; acc[11] += pj * v2.w;
                acc[12] += pj * v3.x; acc[13] += pj * v3.y;
                acc[14] += pj * v3.z; acc[15] += pj * v3.w;
            }
            m = mnew;
        }
    }

    float inv = 1.f / l;
    // O layout [B, L, D]: row (b, qg), cols h*64 + t*16 ..
    float* Op = O + ((size_t)(b * SEQ_L + qg) * DIM) + h * DHEAD + t * 16;
#pragma unroll
    for (int d = 0; d < 16; d++) Op[d] = acc[d] * inv;
}

// ---------------------------------------------------------------------------
extern "C" void kernel_launch(void* const* d_in, const int* in_sizes, int n_in,
                              void* d_out, int out_size)
{
    const float* q  = (const float*)d_in[0];
    const float* k  = (const float*)d_in[1];
    const float* v  = (const float*)d_in[2];
    // d_in[3] = mask (causal triu) — applied analytically, not read
    const float* Wq = (const float*)d_in[4];
    const float* bq = (const float*)d_in[5];
    const float* Wk = (const float*)d_in[6];
    const float* bk = (const float*)d_in[7];
    const float* Wv = (const float*)d_in[8];
    const float* bv = (const float*)d_in[9];
    const float* Wo = (const float*)d_in[10];
    const float* bo = (const float*)d_in[11];

    float *gq, *gk, *gv, *go;
    cudaGetSymbolAddress((void**)&gq, g_Q);
    cudaGetSymbolAddress((void**)&gk, g_K);
    cudaGetSymbolAddress((void**)&gv, g_V);
    cudaGetSymbolAddress((void**)&go, g_O);

    const int M = BATCH * SEQ_L;   // 4096
    dim3 ggrid(DIM / 128, M / 128);   // (8, 32)

    gemm_bias<<<ggrid, 256>>>(q, Wq, bq, gq, M, DIM, DIM, 1);
    gemm_bias<<<ggrid, 256>>>(k, Wk, bk, gk, M, DIM, DIM, 1);
    gemm_bias<<<ggrid, 256>>>(v, Wv, bv, gv, M, DIM, DIM, 1);

    attn_kernel<<<dim3(SEQ_L / 64, NHEAD, BATCH), 256>>>(gq, gk, gv, go);

    gemm_bias<<<ggrid, 256>>>(go, Wo, bo, (float*)d_out, M, DIM, DIM, 0);
}

// round 3
// speedup vs baseline: 1.0081x; 1.0046x over previous
#include <cuda_runtime.h>

#define SEQ_L 2048
#define DIM 1024
#define NHEAD 16
#define DHEAD 64
#define BATCH 2

// Scratch (allocation-free): Q/K/V in [B,H,L,DH], O in [B,L,D]
__device__ float g_Q[BATCH * NHEAD * SEQ_L * DHEAD];
__device__ float g_K[BATCH * NHEAD * SEQ_L * DHEAD];
__device__ float g_V[BATCH * NHEAD * SEQ_L * DHEAD];
__device__ float g_O[BATCH * SEQ_L * DIM];

// ---------------------------------------------------------------------------
// Tiled SGEMM: out = X[M,K] @ W[K,N] + bias[N]
// 128x128 tile, BK=8, 256 threads, 8x8 register micro-tile (split 4+4).
// remap=1: scatter into [B,H,L,DH] layout; remap=0: row-major [M,N].
// ---------------------------------------------------------------------------
__global__ __launch_bounds__(256) void gemm_bias(
    const float* __restrict__ X, const float* __restrict__ W,
    const float* __restrict__ bias, float* __restrict__ out,
    int M, int Kdim, int N, int remap)
{
    __shared__ float As[8][128];   // transposed A tile: As[k][m]
    __shared__ float Bs[8][128];

    const int tid = threadIdx.x;
    const int bm = blockIdx.y * 128;
    const int bn = blockIdx.x * 128;
    const int tx = tid & 15;
    const int ty = tid >> 4;

    const int arow = tid >> 1;          // 0..127
    const int acol = (tid & 1) << 2;    // 0 or 4
    const int brow = tid >> 5;          // 0..7
    const int bcol = (tid & 31) << 2;   // 0..124

    const float* Xp = X + (size_t)(bm + arow) * Kdim + acol;
    const float* Wp = W + (size_t)brow * N + bn + bcol;

    float acc[8][8];
#pragma unroll
    for (int i = 0; i < 8; i++)
#pragma unroll
        for (int j = 0; j < 8; j++) acc[i][j] = 0.f;

    for (int k0 = 0; k0 < Kdim; k0 += 8) {
        float4 a = *(const float4*)Xp;
        float4 bb = *(const float4*)Wp;
        As[acol + 0][arow] = a.x;
        As[acol + 1][arow] = a.y;
        As[acol + 2][arow] = a.z;
        As[acol + 3][arow] = a.w;
        *(float4*)&Bs[brow][bcol] = bb;
        __syncthreads();
#pragma unroll
        for (int kk = 0; kk < 8; kk++) {
            float ra[8], rb[8];
            *(float4*)&ra[0] = *(const float4*)&As[kk][ty * 4];
            *(float4*)&ra[4] = *(const float4*)&As[kk][64 + ty * 4];
            *(float4*)&rb[0] = *(const float4*)&Bs[kk][tx * 4];
            *(float4*)&rb[4] = *(const float4*)&Bs[kk][64 + tx * 4];
#pragma unroll
            for (int i = 0; i < 8; i++)
#pragma unroll
                for (int j = 0; j < 8; j++) acc[i][j] += ra[i] * rb[j];
        }
        __syncthreads();
        Xp += 8;
        Wp += (size_t)8 * N;
    }

#pragma unroll
    for (int i = 0; i < 8; i++) {
        int row = bm + ((i < 4) ? (ty * 4 + i) : (64 + ty * 4 + i - 4));
#pragma unroll
        for (int j = 0; j < 8; j++) {
            int col = bn + ((j < 4) ? (tx * 4 + j) : (64 + tx * 4 + j - 4));
            float val = acc[i][j] + bias[col];
            if (remap) {
                // row -> (b, l);  col -> (h, dh);  out layout [B,H,L,DH]
                int b = row >> 11;           // L = 2048 = 2^11
                int l = row & (SEQ_L - 1);
                int h = col >> 6;            // DH = 64
                int dh = col & 63;
                out[((((size_t)b * NHEAD + h) * SEQ_L + l) << 6) + dh] = val;
            } else {
                out[(size_t)row * N + col] = val;
            }
        }
    }
}

// ---------------------------------------------------------------------------
// Causal flash attention, fp32 SIMT.
// Grid: (L/64, H, B). Block: 256 threads = 64 rows x 4-thread teams.
// Each team thread owns 16 of the 64 head dims. Online softmax in chunks of 16.
// ---------------------------------------------------------------------------
__global__ __launch_bounds__(256) void attn_kernel(
    const float* __restrict__ Q, const float* __restrict__ K,
    const float* __restrict__ V, float* __restrict__ O)
{
    __shared__ float sQ[64][64];
    __shared__ float sK[64][64];
    __shared__ float sV[64][64];

    const int qb = blockIdx.x;
    const int h = blockIdx.y;
    const int b = blockIdx.z;
    const int tid = threadIdx.x;
    const int r = tid >> 2;   // q-row within tile 0..63
    const int t = tid & 3;    // team lane: owns dims [t*16, t*16+16)

    const size_t headOff = (size_t)(b * NHEAD + h) * SEQ_L * DHEAD;
    const float* Qb = Q + headOff + (size_t)qb * 64 * DHEAD;

    // Load Q tile (64x64 floats, 4 float4 per thread)
    for (int i = tid; i < 64 * 16; i += 256) {
        int row = i >> 4;
        int c4 = (i & 15) << 2;
        *(float4*)&sQ[row][c4] = *(const float4*)(Qb + row * DHEAD + c4);
    }
    __syncthreads();

    float qreg[16];
#pragma unroll
    for (int d = 0; d < 16; d++) qreg[d] = sQ[r][t * 16 + d];

    float acc[16];
#pragma unroll
    for (int d = 0; d < 16; d++) acc[d] = 0.f;
    float m = -3.0e38f;
    float l = 0.f;
    const int qg = qb * 64 + r;   // global q index

    for (int kb = 0; kb <= qb; kb++) {
        __syncthreads();   // protect sK/sV (and sQ on first iter) from overwrite
        const float* Kt = K + headOff + (size_t)kb * 64 * DHEAD;
        const float* Vt = V + headOff + (size_t)kb * 64 * DHEAD;
        for (int i = tid; i < 64 * 16; i += 256) {
            int row = i >> 4;
            int c4 = (i & 15) << 2;
            *(float4*)&sK[row][c4] = *(const float4*)(Kt + row * DHEAD + c4);
            *(float4*)&sV[row][c4] = *(const float4*)(Vt + row * DHEAD + c4);
        }
        __syncthreads();

        const bool diag = (kb == qb);
        const int kb64 = kb * 64;

        for (int jc = 0; jc < 64; jc += 16) {
            float s[16];
#pragma unroll
            for (int jj = 0; jj < 16; jj++) {
                int j = jc + jj;
                const float4* kr = (const float4*)&sK[j][t * 16];
                float4 k0 = kr[0], k1 = kr[1], k2 = kr[2], k3 = kr[3];
                float p = qreg[0] * k0.x + qreg[1] * k0.y + qreg[2] * k0.z + qreg[3] * k0.w
                        + qreg[4] * k1.x + qreg[5] * k1.y + qreg[6] * k1.z + qreg[7] * k1.w
                        + qreg[8] * k2.x + qreg[9] * k2.y + qreg[10] * k2.z + qreg[11] * k2.w
                        + qreg[12] * k3.x + qreg[13] * k3.y + qreg[14] * k3.z + qreg[15] * k3.w;
                p += __shfl_xor_sync(0xffffffffu, p, 1);
                p += __shfl_xor_sync(0xffffffffu, p, 2);
                p *= 0.125f;   // 1/sqrt(DH)
                if (diag && (kb64 + j > qg)) p = -1e30f;
                s[jj] = p;
            }
            float mc = s[0];
#pragma unroll
            for (int jj = 1; jj < 16; jj++) mc = fmaxf(mc, s[jj]);
            float mnew = fmaxf(m, mc);
            float corr = __expf(m - mnew);
            l *= corr;
#pragma unroll
            for (int d = 0; d < 16; d++) acc[d] *= corr;
#pragma unroll
            for (int jj = 0; jj < 16; jj++) {
                int j = jc + jj;
                float pj = __expf(s[jj] - mnew);
                if (diag && (kb64 + j > qg)) pj = 0.f;  // bulletproof vs all-masked chunk
                l += pj;
                const float4* vr = (const float4*)&sV[j][t * 16];
                float4 v0 = vr[0], v1 = vr[1], v2 = vr[2], v3 = vr[3];
                acc[0] += pj * v0.x;  acc[1] += pj * v0.y;
                acc[2] += pj * v0.z;  acc[3] += pj * v0.w;
                acc[4] += pj * v1.x;  acc[5] += pj * v1.y;
                acc[6] += pj * v1.z;  acc[7] += pj * v1.w;
                acc[8] += pj * v2.x;  acc[9] += pj * v2.y;
                acc[10] += pj * v2.z; acc[11] += pj * v2.w;
                acc[12] += pj * v3.x; acc[13] += pj * v3.y;
                acc[14] += pj * v3.z; acc[15] += pj * v3.w;
            }
            m = mnew;
        }
    }

    float inv = 1.f / l;
    // O layout [B, L, D]: row (b, qg), cols h*64 + t*16 ..
    float* Op = O + ((size_t)(b * SEQ_L + qg) * DIM) + h * DHEAD + t * 16;
#pragma unroll
    for (int d = 0; d < 16; d++) Op[d] = acc[d] * inv;
}

// ---------------------------------------------------------------------------
extern "C" void kernel_launch(void* const* d_in, const int* in_sizes, int n_in,
                              void* d_out, int out_size)
{
    const float* q  = (const float*)d_in[0];
    const float* k  = (const float*)d_in[1];
    const float* v  = (const float*)d_in[2];
    // d_in[3] = mask (causal triu) — applied analytically, not read
    const float* Wq = (const float*)d_in[4];
    const float* bq = (const float*)d_in[5];
    const float* Wk = (const float*)d_in[6];
    const float* bk = (const float*)d_in[7];
    const float* Wv = (const float*)d_in[8];
    const float* bv = (const float*)d_in[9];
    const float* Wo = (const float*)d_in[10];
    const float* bo = (const float*)d_in[11];

    float *gq, *gk, *gv, *go;
    cudaGetSymbolAddress((void**)&gq, g_Q);
    cudaGetSymbolAddress((void**)&gk, g_K);
    cudaGetSymbolAddress((void**)&gv, g_V);
    cudaGetSymbolAddress((void**)&go, g_O);

    const int M = BATCH * SEQ_L;   // 4096
    dim3 ggrid(DIM / 128, M / 128);   // (8, 32)

    gemm_bias<<<ggrid, 256>>>(q, Wq, bq, gq, M, DIM, DIM, 1);
    gemm_bias<<<ggrid, 256>>>(k, Wk, bk, gk, M, DIM, DIM, 1);
    gemm_bias<<<ggrid, 256>>>(v, Wv, bv, gv, M, DIM, DIM, 1);

    attn_kernel<<<dim3(SEQ_L / 64, NHEAD, BATCH), 256>>>(gq, gk, gv, go);

    gemm_bias<<<ggrid, 256>>>(go, Wo, bo, (float*)d_out, M, DIM, DIM, 0);
}

// round 4
// speedup vs baseline: 1.0130x; 1.0048x over previous
#include <cuda_runtime.h>

#define SEQ_L 2048
#define DIM 1024
#define NHEAD 16
#define DHEAD 64
#define BATCH 2

// Scratch (allocation-free): Q/K/V in [B,H,L,DH], O in [B,L,D]
__device__ float g_Q[BATCH * NHEAD * SEQ_L * DHEAD];
__device__ float g_K[BATCH * NHEAD * SEQ_L * DHEAD];
__device__ float g_V[BATCH * NHEAD * SEQ_L * DHEAD];
__device__ float g_O[BATCH * SEQ_L * DIM];

// ---------------------------------------------------------------------------
// Tiled SGEMM: out = X[M,K] @ W[K,N] + bias[N]
// 128x128 tile, BK=8, 256 threads, 8x8 register micro-tile (split 4+4).
// remap=1: scatter into [B,H,L,DH] layout; remap=0: row-major [M,N].
// ---------------------------------------------------------------------------
__global__ __launch_bounds__(256) void gemm_bias(
    const float* __restrict__ X, const float* __restrict__ W,
    const float* __restrict__ bias, float* __restrict__ out,
    int M, int Kdim, int N, int remap)
{
    __shared__ float As[8][128];   // transposed A tile: As[k][m]
    __shared__ float Bs[8][128];

    const int tid = threadIdx.x;
    const int bm = blockIdx.y * 128;
    const int bn = blockIdx.x * 128;
    const int tx = tid & 15;
    const int ty = tid >> 4;

    const int arow = tid >> 1;          // 0..127
    const int acol = (tid & 1) << 2;    // 0 or 4
    const int brow = tid >> 5;          // 0..7
    const int bcol = (tid & 31) << 2;   // 0..124

    const float* Xp = X + (size_t)(bm + arow) * Kdim + acol;
    const float* Wp = W + (size_t)brow * N + bn + bcol;

    float acc[8][8];
#pragma unroll
    for (int i = 0; i < 8; i++)
#pragma unroll
        for (int j = 0; j < 8; j++) acc[i][j] = 0.f;

    for (int k0 = 0; k0 < Kdim; k0 += 8) {
        float4 a = *(const float4*)Xp;
        float4 bb = *(const float4*)Wp;
        As[acol + 0][arow] = a.x;
        As[acol + 1][arow] = a.y;
        As[acol + 2][arow] = a.z;
        As[acol + 3][arow] = a.w;
        *(float4*)&Bs[brow][bcol] = bb;
        __syncthreads();
#pragma unroll
        for (int kk = 0; kk < 8; kk++) {
            float ra[8], rb[8];
            *(float4*)&ra[0] = *(const float4*)&As[kk][ty * 4];
            *(float4*)&ra[4] = *(const float4*)&As[kk][64 + ty * 4];
            *(float4*)&rb[0] = *(const float4*)&Bs[kk][tx * 4];
            *(float4*)&rb[4] = *(const float4*)&Bs[kk][64 + tx * 4];
#pragma unroll
            for (int i = 0; i < 8; i++)
#pragma unroll
                for (int j = 0; j < 8; j++) acc[i][j] += ra[i] * rb[j];
        }
        __syncthreads();
        Xp += 8;
        Wp += (size_t)8 * N;
    }

#pragma unroll
    for (int i = 0; i < 8; i++) {
        int row = bm + ((i < 4) ? (ty * 4 + i) : (64 + ty * 4 + i - 4));
#pragma unroll
        for (int j = 0; j < 8; j++) {
            int col = bn + ((j < 4) ? (tx * 4 + j) : (64 + tx * 4 + j - 4));
            float val = acc[i][j] + bias[col];
            if (remap) {
                // row -> (b, l);  col -> (h, dh);  out layout [B,H,L,DH]
                int b = row >> 11;           // L = 2048 = 2^11
                int l = row & (SEQ_L - 1);
                int h = col >> 6;            // DH = 64
                int dh = col & 63;
                out[((((size_t)b * NHEAD + h) * SEQ_L + l) << 6) + dh] = val;
            } else {
                out[(size_t)row * N + col] = val;
            }
        }
    }
}

// ---------------------------------------------------------------------------
// Causal flash attention, fp32 SIMT.
// Grid: (L/64, H, B). Block: 256 threads = 64 rows x 4-thread teams.
// Each team thread owns 16 of the 64 head dims. Online softmax in chunks of 16.
// ---------------------------------------------------------------------------
__global__ __launch_bounds__(256) void attn_kernel(
    const float* __restrict__ Q, const float* __restrict__ K,
    const float* __restrict__ V, float* __restrict__ O)
{
    __shared__ float sQ[64][64];
    __shared__ float sK[64][64];
    __shared__ float sV[64][64];

    const int qb = blockIdx.x;
    const int h = blockIdx.y;
    const int b = blockIdx.z;
    const int tid = threadIdx.x;
    const int r = tid >> 2;   // q-row within tile 0..63
    const int t = tid & 3;    // team lane: owns dims [t*16, t*16+16)

    const size_t headOff = (size_t)(b * NHEAD + h) * SEQ_L * DHEAD;
    const float* Qb = Q + headOff + (size_t)qb * 64 * DHEAD;

    // Load Q tile (64x64 floats, 4 float4 per thread)
    for (int i = tid; i < 64 * 16; i += 256) {
        int row = i >> 4;
        int c4 = (i & 15) << 2;
        *(float4*)&sQ[row][c4] = *(const float4*)(Qb + row * DHEAD + c4);
    }
    __syncthreads();

    float qreg[16];
#pragma unroll
    for (int d = 0; d < 16; d++) qreg[d] = sQ[r][t * 16 + d];

    float acc[16];
#pragma unroll
    for (int d = 0; d < 16; d++) acc[d] = 0.f;
    float m = -3.0e38f;
    float l = 0.f;
    const int qg = qb * 64 + r;   // global q index

    for (int kb = 0; kb <= qb; kb++) {
        __syncthreads();   // protect sK/sV (and sQ on first iter) from overwrite
        const float* Kt = K + headOff + (size_t)kb * 64 * DHEAD;
        const float* Vt = V + headOff + (size_t)kb * 64 * DHEAD;
        for (int i = tid; i < 64 * 16; i += 256) {
            int row = i >> 4;
            int c4 = (i & 15) << 2;
            *(float4*)&sK[row][c4] = *(const float4*)(Kt + row * DHEAD + c4);
            *(float4*)&sV[row][c4] = *(const float4*)(Vt + row * DHEAD + c4);
        }
        __syncthreads();

        const bool diag = (kb == qb);
        const int kb64 = kb * 64;

        for (int jc = 0; jc < 64; jc += 16) {
            float s[16];
#pragma unroll
            for (int jj = 0; jj < 16; jj++) {
                int j = jc + jj;
                const float4* kr = (const float4*)&sK[j][t * 16];
                float4 k0 = kr[0], k1 = kr[1], k2 = kr[2], k3 = kr[3];
                float p = qreg[0] * k0.x + qreg[1] * k0.y + qreg[2] * k0.z + qreg[3] * k0.w
                        + qreg[4] * k1.x + qreg[5] * k1.y + qreg[6] * k1.z + qreg[7] * k1.w
                        + qreg[8] * k2.x + qreg[9] * k2.y + qreg[10] * k2.z + qreg[11] * k2.w
                        + qreg[12] * k3.x + qreg[13] * k3.y + qreg[14] * k3.z + qreg[15] * k3.w;
                p += __shfl_xor_sync(0xffffffffu, p, 1);
                p += __shfl_xor_sync(0xffffffffu, p, 2);
                p *= 0.125f;   // 1/sqrt(DH)
                if (diag && (kb64 + j > qg)) p = -1e30f;
                s[jj] = p;
            }
            float mc = s[0];
#pragma unroll
            for (int jj = 1; jj < 16; jj++) mc = fmaxf(mc, s[jj]);
            float mnew = fmaxf(m, mc);
            float corr = __expf(m - mnew);
            l *= corr;
#pragma unroll
            for (int d = 0; d < 16; d++) acc[d] *= corr;
#pragma unroll
            for (int jj = 0; jj < 16; jj++) {
                int j = jc + jj;
                float pj = __expf(s[jj] - mnew);
                if (diag && (kb64 + j > qg)) pj = 0.f;  // bulletproof vs all-masked chunk
                l += pj;
                const float4* vr = (const float4*)&sV[j][t * 16];
                float4 v0 = vr[0], v1 = vr[1], v2 = vr[2], v3 = vr[3];
                acc[0] += pj * v0.x;  acc[1] += pj * v0.y;
                acc[2] += pj * v0.z;  acc[3] += pj * v0.w;
                acc[4] += pj * v1.x;  acc[5] += pj * v1.y;
                acc[6] += pj * v1.z;  acc[7] += pj * v1.w;
                acc[8] += pj * v2.x;  acc[9] += pj * v2.y;
                acc[10] += pj * v2.z; acc[11] += pj * v2.w;
                acc[12] += pj * v3.x; acc[13] += pj * v3.y;
                acc[14] += pj * v3.z; acc[15] += pj * v3.w;
            }
            m = mnew;
        }
    }

    float inv = 1.f / l;
    // O layout [B, L, D]: row (b, qg), cols h*64 + t*16 ..
    float* Op = O + ((size_t)(b * SEQ_L + qg) * DIM) + h * DHEAD + t * 16;
#pragma unroll
    for (int d = 0; d < 16; d++) Op[d] = acc[d] * inv;
}

// ---------------------------------------------------------------------------
extern "C" void kernel_launch(void* const* d_in, const int* in_sizes, int n_in,
                              void* d_out, int out_size)
{
    const float* q  = (const float*)d_in[0];
    const float* k  = (const float*)d_in[1];
    const float* v  = (const float*)d_in[2];
    // d_in[3] = mask (causal triu) — applied analytically, not read
    const float* Wq = (const float*)d_in[4];
    const float* bq = (const float*)d_in[5];
    const float* Wk = (const float*)d_in[6];
    const float* bk = (const float*)d_in[7];
    const float* Wv = (const float*)d_in[8];
    const float* bv = (const float*)d_in[9];
    const float* Wo = (const float*)d_in[10];
    const float* bo = (const float*)d_in[11];

    float *gq, *gk, *gv, *go;
    cudaGetSymbolAddress((void**)&gq, g_Q);
    cudaGetSymbolAddress((void**)&gk, g_K);
    cudaGetSymbolAddress((void**)&gv, g_V);
    cudaGetSymbolAddress((void**)&go, g_O);

    const int M = BATCH * SEQ_L;   // 4096
    dim3 ggrid(DIM / 128, M / 128);   // (8, 32)

    gemm_bias<<<ggrid, 256>>>(q, Wq, bq, gq, M, DIM, DIM, 1);
    gemm_bias<<<ggrid, 256>>>(k, Wk, bk, gk, M, DIM, DIM, 1);
    gemm_bias<<<ggrid, 256>>>(v, Wv, bv, gv, M, DIM, DIM, 1);

    attn_kernel<<<dim3(SEQ_L / 64, NHEAD, BATCH), 256>>>(gq, gk, gv, go);

    gemm_bias<<<ggrid, 256>>>(go, Wo, bo, (float*)d_out, M, DIM, DIM, 0);
}

// round 5
// speedup vs baseline: 1.0288x; 1.0156x over previous
#include <cuda_runtime.h>

#define SEQ_L 2048
#define DIM 1024
#define NHEAD 16
#define DHEAD 64
#define BATCH 2

// Scratch (allocation-free): Q/K/V in [B,H,L,DH], O in [B,L,D]
__device__ float g_Q[BATCH * NHEAD * SEQ_L * DHEAD];
__device__ float g_K[BATCH * NHEAD * SEQ_L * DHEAD];
__device__ float g_V[BATCH * NHEAD * SEQ_L * DHEAD];
__device__ float g_O[BATCH * SEQ_L * DIM];

// ---------------------------------------------------------------------------
// Tiled SGEMM: out = X[M,K] @ W[K,N] + bias[N]
// 128x128 tile, BK=8, 256 threads, 8x8 register micro-tile (split 4+4).
// remap=1: scatter into [B,H,L,DH] layout; remap=0: row-major [M,N].
// ---------------------------------------------------------------------------
__global__ __launch_bounds__(256) void gemm_bias(
    const float* __restrict__ X, const float* __restrict__ W,
    const float* __restrict__ bias, float* __restrict__ out,
    int M, int Kdim, int N, int remap)
{
    __shared__ float As[8][128];   // transposed A tile: As[k][m]
    __shared__ float Bs[8][128];

    const int tid = threadIdx.x;
    const int bm = blockIdx.y * 128;
    const int bn = blockIdx.x * 128;
    const int tx = tid & 15;
    const int ty = tid >> 4;

    const int arow = tid >> 1;          // 0..127
    const int acol = (tid & 1) << 2;    // 0 or 4
    const int brow = tid >> 5;          // 0..7
    const int bcol = (tid & 31) << 2;   // 0..124

    const float* Xp = X + (size_t)(bm + arow) * Kdim + acol;
    const float* Wp = W + (size_t)brow * N + bn + bcol;

    float acc[8][8];
#pragma unroll
    for (int i = 0; i < 8; i++)
#pragma unroll
        for (int j = 0; j < 8; j++) acc[i][j] = 0.f;

    for (int k0 = 0; k0 < Kdim; k0 += 8) {
        float4 a = *(const float4*)Xp;
        float4 bb = *(const float4*)Wp;
        As[acol + 0][arow] = a.x;
        As[acol + 1][arow] = a.y;
        As[acol + 2][arow] = a.z;
        As[acol + 3][arow] = a.w;
        *(float4*)&Bs[brow][bcol] = bb;
        __syncthreads();
#pragma unroll
        for (int kk = 0; kk < 8; kk++) {
            float ra[8], rb[8];
            *(float4*)&ra[0] = *(const float4*)&As[kk][ty * 4];
            *(float4*)&ra[4] = *(const float4*)&As[kk][64 + ty * 4];
            *(float4*)&rb[0] = *(const float4*)&Bs[kk][tx * 4];
            *(float4*)&rb[4] = *(const float4*)&Bs[kk][64 + tx * 4];
#pragma unroll
            for (int i = 0; i < 8; i++)
#pragma unroll
                for (int j = 0; j < 8; j++) acc[i][j] += ra[i] * rb[j];
        }
        __syncthreads();
        Xp += 8;
        Wp += (size_t)8 * N;
    }

#pragma unroll
    for (int i = 0; i < 8; i++) {
        int row = bm + ((i < 4) ? (ty * 4 + i) : (64 + ty * 4 + i - 4));
#pragma unroll
        for (int j = 0; j < 8; j++) {
            int col = bn + ((j < 4) ? (tx * 4 + j) : (64 + tx * 4 + j - 4));
            float val = acc[i][j] + bias[col];
            if (remap) {
                // row -> (b, l);  col -> (h, dh);  out layout [B,H,L,DH]
                int b = row >> 11;           // L = 2048 = 2^11
                int l = row & (SEQ_L - 1);
                int h = col >> 6;            // DH = 64
                int dh = col & 63;
                out[((((size_t)b * NHEAD + h) * SEQ_L + l) << 6) + dh] = val;
            } else {
                out[(size_t)row * N + col] = val;
            }
        }
    }
}

// ---------------------------------------------------------------------------
// Causal flash attention, fp32 SIMT.
// Grid: (L/64, H, B). Block: 256 threads = 64 rows x 4-thread teams.
// Each team thread owns 16 of the 64 head dims. Online softmax in chunks of 16.
// ---------------------------------------------------------------------------
__global__ __launch_bounds__(256) void attn_kernel(
    const float* __restrict__ Q, const float* __restrict__ K,
    const float* __restrict__ V, float* __restrict__ O)
{
    __shared__ float sQ[64][64];
    __shared__ float sK[64][64];
    __shared__ float sV[64][64];

    const int qb = blockIdx.x;
    const int h = blockIdx.y;
    const int b = blockIdx.z;
    const int tid = threadIdx.x;
    const int r = tid >> 2;   // q-row within tile 0..63
    const int t = tid & 3;    // team lane: owns dims [t*16, t*16+16)

    const size_t headOff = (size_t)(b * NHEAD + h) * SEQ_L * DHEAD;
    const float* Qb = Q + headOff + (size_t)qb * 64 * DHEAD;

    // Load Q tile (64x64 floats, 4 float4 per thread)
    for (int i = tid; i < 64 * 16; i += 256) {
        int row = i >> 4;
        int c4 = (i & 15) << 2;
        *(float4*)&sQ[row][c4] = *(const float4*)(Qb + row * DHEAD + c4);
    }
    __syncthreads();

    float qreg[16];
#pragma unroll
    for (int d = 0; d < 16; d++) qreg[d] = sQ[r][t * 16 + d];

    float acc[16];
#pragma unroll
    for (int d = 0; d < 16; d++) acc[d] = 0.f;
    float m = -3.0e38f;
    float l = 0.f;
    const int qg = qb * 64 + r;   // global q index

    for (int kb = 0; kb <= qb; kb++) {
        __syncthreads();   // protect sK/sV (and sQ on first iter) from overwrite
        const float* Kt = K + headOff + (size_t)kb * 64 * DHEAD;
        const float* Vt = V + headOff + (size_t)kb * 64 * DHEAD;
        for (int i = tid; i < 64 * 16; i += 256) {
            int row = i >> 4;
            int c4 = (i & 15) << 2;
            *(float4*)&sK[row][c4] = *(const float4*)(Kt + row * DHEAD + c4);
            *(float4*)&sV[row][c4] = *(const float4*)(Vt + row * DHEAD + c4);
        }
        __syncthreads();

        const bool diag = (kb == qb);
        const int kb64 = kb * 64;

        for (int jc = 0; jc < 64; jc += 16) {
            float s[16];
#pragma unroll
            for (int jj = 0; jj < 16; jj++) {
                int j = jc + jj;
                const float4* kr = (const float4*)&sK[j][t * 16];
                float4 k0 = kr[0], k1 = kr[1], k2 = kr[2], k3 = kr[3];
                float p = qreg[0] * k0.x + qreg[1] * k0.y + qreg[2] * k0.z + qreg[3] * k0.w
                        + qreg[4] * k1.x + qreg[5] * k1.y + qreg[6] * k1.z + qreg[7] * k1.w
                        + qreg[8] * k2.x + qreg[9] * k2.y + qreg[10] * k2.z + qreg[11] * k2.w
                        + qreg[12] * k3.x + qreg[13] * k3.y + qreg[14] * k3.z + qreg[15] * k3.w;
                p += __shfl_xor_sync(0xffffffffu, p, 1);
                p += __shfl_xor_sync(0xffffffffu, p, 2);
                p *= 0.125f;   // 1/sqrt(DH)
                if (diag && (kb64 + j > qg)) p = -1e30f;
                s[jj] = p;
            }
            float mc = s[0];
#pragma unroll
            for (int jj = 1; jj < 16; jj++) mc = fmaxf(mc, s[jj]);
            float mnew = fmaxf(m, mc);
            float corr = __expf(m - mnew);
            l *= corr;
#pragma unroll
            for (int d = 0; d < 16; d++) acc[d] *= corr;
#pragma unroll
            for (int jj = 0; jj < 16; jj++) {
                int j = jc + jj;
                float pj = __expf(s[jj] - mnew);
                if (diag && (kb64 + j > qg)) pj = 0.f;  // bulletproof vs all-masked chunk
                l += pj;
                const float4* vr = (const float4*)&sV[j][t * 16];
                float4 v0 = vr[0], v1 = vr[1], v2 = vr[2], v3 = vr[3];
                acc[0] += pj * v0.x;  acc[1] += pj * v0.y;
                acc[2] += pj * v0.z;  acc[3] += pj * v0.w;
                acc[4] += pj * v1.x;  acc[5] += pj * v1.y;
                acc[6] += pj * v1.z;  acc[7] += pj * v1.w;
                acc[8] += pj * v2.x;  acc[9] += pj * v2.y;
                acc[10] += pj * v2.z; acc[11] += pj * v2.w;
                acc[12] += pj * v3.x; acc[13] += pj * v3.y;
                acc[14] += pj * v3.z; acc[15] += pj * v3.w;
            }
            m = mnew;
        }
    }

    float inv = 1.f / l;
    // O layout [B, L, D]: row (b, qg), cols h*64 + t*16 ..
    float* Op = O + ((size_t)(b * SEQ_L + qg) * DIM) + h * DHEAD + t * 16;
#pragma unroll
    for (int d = 0; d < 16; d++) Op[d] = acc[d] * inv;
}

// ---------------------------------------------------------------------------
extern "C" void kernel_launch(void* const* d_in, const int* in_sizes, int n_in,
                              void* d_out, int out_size)
{
    const float* q  = (const float*)d_in[0];
    const float* k  = (const float*)d_in[1];
    const float* v  = (const float*)d_in[2];
    // d_in[3] = mask (causal triu) — applied analytically, not read
    const float* Wq = (const float*)d_in[4];
    const float* bq = (const float*)d_in[5];
    const float* Wk = (const float*)d_in[6];
    const float* bk = (const float*)d_in[7];
    const float* Wv = (const float*)d_in[8];
    const float* bv = (const float*)d_in[9];
    const float* Wo = (const float*)d_in[10];
    const float* bo = (const float*)d_in[11];

    float *gq, *gk, *gv, *go;
    cudaGetSymbolAddress((void**)&gq, g_Q);
    cudaGetSymbolAddress((void**)&gk, g_K);
    cudaGetSymbolAddress((void**)&gv, g_V);
    cudaGetSymbolAddress((void**)&go, g_O);

    const int M = BATCH * SEQ_L;   // 4096
    dim3 ggrid(DIM / 128, M / 128);   // (8, 32)

    gemm_bias<<<ggrid, 256>>>(q, Wq, bq, gq, M, DIM, DIM, 1);
    gemm_bias<<<ggrid, 256>>>(k, Wk, bk, gk, M, DIM, DIM, 1);
    gemm_bias<<<ggrid, 256>>>(v, Wv, bv, gv, M, DIM, DIM, 1);

    attn_kernel<<<dim3(SEQ_L / 64, NHEAD, BATCH), 256>>>(gq, gk, gv, go);

    gemm_bias<<<ggrid, 256>>>(go, Wo, bo, (float*)d_out, M, DIM, DIM, 0);
}

// round 8
// speedup vs baseline: 1.9204x; 1.8666x over previous
#include <cuda_runtime.h>
#include <cstdint>

#define SEQ_L 2048
#define DIM 1024
#define NHEAD 16
#define DHEAD 64
#define BATCH 2

// Scratch (allocation-free)
__device__ float g_Q[BATCH * NHEAD * SEQ_L * DHEAD];
__device__ float g_K[BATCH * NHEAD * SEQ_L * DHEAD];
__device__ float g_V[BATCH * NHEAD * SEQ_L * DHEAD];
__device__ float g_O[BATCH * SEQ_L * DIM];
__device__ float g_Wt[4 * DIM * DIM];   // transposed weights: Wt[n*K+k] = W[k*N+n]

// ---------------------------------------------------------------------------
__device__ __forceinline__ unsigned smem_u32(const void* p) {
    unsigned a;
    asm("{ .reg .u64 t; cvta.to.shared.u64 t, %1; cvt.u32.u64 %0, t; }"
        : "=r"(a) : "l"(p));
    return a;
}

__device__ __forceinline__ unsigned f2tf32(float f) {
    unsigned u;
    asm("cvt.rna.tf32.f32 %0, %1;" : "=r"(u) : "f"(f));
    return u;
}

__device__ __forceinline__ void mma_tf32(float* c, const unsigned* a, const unsigned* b) {
    asm volatile(
        "mma.sync.aligned.m16n8k8.row.col.f32.tf32.tf32.f32 "
        "{%0,%1,%2,%3}, {%4,%5,%6,%7}, {%8,%9}, {%0,%1,%2,%3};"
        : "+f"(c[0]), "+f"(c[1]), "+f"(c[2]), "+f"(c[3])
        : "r"(a[0]), "r"(a[1]), "r"(a[2]), "r"(a[3]), "r"(b[0]), "r"(b[1]));
}

// ---------------------------------------------------------------------------
// Batched 1024x1024 transpose: g_Wt[z] = W_z^T
// ---------------------------------------------------------------------------
__global__ __launch_bounds__(256) void transpose4(
    const float* __restrict__ w0, const float* __restrict__ w1,
    const float* __restrict__ w2, const float* __restrict__ w3,
    float* __restrict__ out)
{
    __shared__ float tile[32][33];
    const float* in = (blockIdx.z == 0) ? w0 : (blockIdx.z == 1) ? w1
                    : (blockIdx.z == 2) ? w2 : w3;
    float* o = out + (size_t)blockIdx.z * DIM * DIM;
    const int x = blockIdx.x * 32;   // n base
    const int y = blockIdx.y * 32;   // k base
    const int tx = threadIdx.x, ty = threadIdx.y;
#pragma unroll
    for (int i = 0; i < 32; i += 8)
        tile[ty + i][tx] = in[(size_t)(y + ty + i) * DIM + x + tx];
    __syncthreads();
#pragma unroll
    for (int i = 0; i < 32; i += 8)
        o[(size_t)(x + ty + i) * DIM + y + tx] = tile[tx][ty + i];
}

// ---------------------------------------------------------------------------
// tf32 mma.sync GEMM: out = X[M,1024] @ Wt^T + bias   (Wt is [N,K], K-major)
// CTA 128x128, BK=16, 256 threads = 8 warps of 64x32 warp tiles.
// cp.async double-buffered smem; pad-20 rows (conflict-free fragment LDS).
// ---------------------------------------------------------------------------
#define BK 16

__global__ __launch_bounds__(256) void gemm_mma(
    const float* __restrict__ X, const float* __restrict__ Wt,
    const float* __restrict__ bias, float* __restrict__ out,
    int Kdim, int remap)
{
    __shared__ __align__(16) float As[2][128][20];
    __shared__ __align__(16) float Bs[2][128][20];

    const int tid = threadIdx.x;
    const int wid = tid >> 5, lid = tid & 31;
    const int wm = wid >> 2;        // 0..1  (64-row band)
    const int wn = wid & 3;         // 0..3  (32-col band)
    const int gid = lid >> 2;       // 0..7
    const int tig = lid & 3;        // 0..3
    const int bm = blockIdx.y * 128;
    const int bn = blockIdx.x * 128;

    float acc[4][4][4];
#pragma unroll
    for (int mf = 0; mf < 4; mf++)
#pragma unroll
        for (int nf = 0; nf < 4; nf++)
#pragma unroll
            for (int r = 0; r < 4; r++) acc[mf][nf][r] = 0.f;

    // per-thread gmem->smem mapping: 2 float4 per tile each for A and B
    const int ldrow0 = tid >> 2;               // 0..63
    const int ldk4 = (tid & 3) << 2;           // 0,4,8,12

    const int nchunk = Kdim / BK;              // 64

    // ---- prologue: stage chunk 0 into buf 0
    {
        const int k0 = 0;
#pragma unroll
        for (int i = 0; i < 2; i++) {
            int row = ldrow0 + i * 64;
            unsigned da = smem_u32(&As[0][row][ldk4]);
            unsigned db = smem_u32(&Bs[0][row][ldk4]);
            const float* sa = X + (size_t)(bm + row) * Kdim + k0 + ldk4;
            const float* sb = Wt + (size_t)(bn + row) * Kdim + k0 + ldk4;
            asm volatile("cp.async.ca.shared.global [%0], [%1], 16;" :: "r"(da), "l"(sa));
            asm volatile("cp.async.ca.shared.global [%0], [%1], 16;" :: "r"(db), "l"(sb));
        }
        asm volatile("cp.async.commit_group;");
    }

    for (int c = 0; c < nchunk; c++) {
        const int buf = c & 1;
        if (c + 1 < nchunk) {
            const int k0 = (c + 1) * BK;
            const int nb = buf ^ 1;
#pragma unroll
            for (int i = 0; i < 2; i++) {
                int row = ldrow0 + i * 64;
                unsigned da = smem_u32(&As[nb][row][ldk4]);
                unsigned db = smem_u32(&Bs[nb][row][ldk4]);
                const float* sa = X + (size_t)(bm + row) * Kdim + k0 + ldk4;
                const float* sb = Wt + (size_t)(bn + row) * Kdim + k0 + ldk4;
                asm volatile("cp.async.ca.shared.global [%0], [%1], 16;" :: "r"(da), "l"(sa));
                asm volatile("cp.async.ca.shared.global [%0], [%1], 16;" :: "r"(db), "l"(sb));
            }
            asm volatile("cp.async.commit_group;");
            asm volatile("cp.async.wait_group 1;");
        } else {
            asm volatile("cp.async.wait_group 0;");
        }
        __syncthreads();

#pragma unroll
        for (int ks = 0; ks < BK; ks += 8) {
            unsigned af[4][4], bf[4][2];
#pragma unroll
            for (int mf = 0; mf < 4; mf++) {
                int r0 = wm * 64 + mf * 16 + gid;
                af[mf][0] = f2tf32(As[buf][r0][ks + tig]);
                af[mf][1] = f2tf32(As[buf][r0 + 8][ks + tig]);
                af[mf][2] = f2tf32(As[buf][r0][ks + tig + 4]);
                af[mf][3] = f2tf32(As[buf][r0 + 8][ks + tig + 4]);
            }
#pragma unroll
            for (int nf = 0; nf < 4; nf++) {
                int r = wn * 32 + nf * 8 + gid;
                bf[nf][0] = f2tf32(Bs[buf][r][ks + tig]);
                bf[nf][1] = f2tf32(Bs[buf][r][ks + tig + 4]);
            }
#pragma unroll
            for (int mf = 0; mf < 4; mf++)
#pragma unroll
                for (int nf = 0; nf < 4; nf++)
                    mma_tf32(acc[mf][nf], af[mf], bf[nf]);
        }
        __syncthreads();
    }

    // ---- epilogue ----
#pragma unroll
    for (int mf = 0; mf < 4; mf++) {
#pragma unroll
        for (int nf = 0; nf < 4; nf++) {
            int row0 = bm + wm * 64 + mf * 16 + gid;
            int col = bn + wn * 32 + nf * 8 + 2 * tig;
            float b0 = bias[col], b1 = bias[col + 1];
            float2 vtop = make_float2(acc[mf][nf][0] + b0, acc[mf][nf][1] + b1);
            float2 vbot = make_float2(acc[mf][nf][2] + b0, acc[mf][nf][3] + b1);
            if (remap) {
                int h = col >> 6;
                int dh = col & 63;
#pragma unroll
                for (int rr = 0; rr < 2; rr++) {
                    int row = row0 + rr * 8;
                    int b = row >> 11;
                    int l = row & (SEQ_L - 1);
                    size_t idx = ((((size_t)b * NHEAD + h) * SEQ_L + l) << 6) + dh;
                    *(float2*)&out[idx] = rr ? vbot : vtop;
                }
            } else {
                *(float2*)&out[(size_t)row0 * DIM + col] = vtop;
                *(float2*)&out[(size_t)(row0 + 8) * DIM + col] = vbot;
            }
        }
    }
}

// ---------------------------------------------------------------------------
// Causal flash attention, fp32 SIMT, 2 q-rows per thread.
// Grid: (L/128, H, B). Block 256 = 64 row-pairs x 4-thread dim teams.
// smem (dynamic 64KB): sQ[128][64], sK[64][64], sV[64][64]
// ---------------------------------------------------------------------------
__global__ __launch_bounds__(256) void attn_kernel(
    const float* __restrict__ Q, const float* __restrict__ K,
    const float* __restrict__ V, float* __restrict__ O)
{
    extern __shared__ float sa[];
    float* sQ = sa;                  // 128*64
    float* sK = sa + 8192;           // 64*64
    float* sV = sa + 8192 + 4096;    // 64*64

    const int qb = blockIdx.x;
    const int h = blockIdx.y;
    const int b = blockIdx.z;
    const int tid = threadIdx.x;
    const int rp = tid >> 2;
    const int t = tid & 3;

    const size_t headOff = (size_t)(b * NHEAD + h) * SEQ_L * DHEAD;
    const float* Qb = Q + headOff + (size_t)qb * 128 * DHEAD;

    for (int i = tid; i < 128 * 16; i += 256) {
        int row = i >> 4;
        int c4 = (i & 15) << 2;
        *(float4*)&sQ[row * 64 + c4] = *(const float4*)(Qb + row * DHEAD + c4);
    }
    __syncthreads();

    float q0[16], q1[16];
#pragma unroll
    for (int d = 0; d < 16; d++) {
        q0[d] = sQ[rp * 64 + t * 16 + d];
        q1[d] = sQ[(rp + 64) * 64 + t * 16 + d];
    }
    float a0[16], a1[16];
#pragma unroll
    for (int d = 0; d < 16; d++) { a0[d] = 0.f; a1[d] = 0.f; }
    float m0 = -3.0e38f, m1 = -3.0e38f, l0 = 0.f, l1 = 0.f;
    const int qg0 = qb * 128 + rp;
    const int qg1 = qg0 + 64;
    const int nkb = 2 * qb + 2;

    for (int kb = 0; kb < nkb; kb++) {
        __syncthreads();
        const float* Kt = K + headOff + (size_t)kb * 64 * DHEAD;
        const float* Vt = V + headOff + (size_t)kb * 64 * DHEAD;
        for (int i = tid; i < 64 * 16; i += 256) {
            int row = i >> 4;
            int c4 = (i & 15) << 2;
            *(float4*)&sK[row * 64 + c4] = *(const float4*)(Kt + row * DHEAD + c4);
            *(float4*)&sV[row * 64 + c4] = *(const float4*)(Vt + row * DHEAD + c4);
        }
        __syncthreads();
        const int kb64 = kb * 64;

        for (int jc = 0; jc < 64; jc += 16) {
            float s0[16], s1[16];
#pragma unroll
            for (int jj = 0; jj < 16; jj++) {
                int j = jc + jj;
                const float4* kr = (const float4*)&sK[j * 64 + t * 16];
                float4 k0 = kr[0], k1 = kr[1], k2 = kr[2], k3 = kr[3];
                float p0 = q0[0]*k0.x + q0[1]*k0.y + q0[2]*k0.z + q0[3]*k0.w
                         + q0[4]*k1.x + q0[5]*k1.y + q0[6]*k1.z + q0[7]*k1.w
                         + q0[8]*k2.x + q0[9]*k2.y + q0[10]*k2.z + q0[11]*k2.w
                         + q0[12]*k3.x + q0[13]*k3.y + q0[14]*k3.z + q0[15]*k3.w;
                float p1 = q1[0]*k0.x + q1[1]*k0.y + q1[2]*k0.z + q1[3]*k0.w
                         + q1[4]*k1.x + q1[5]*k1.y + q1[6]*k1.z + q1[7]*k1.w
                         + q1[8]*k2.x + q1[9]*k2.y + q1[10]*k2.z + q1[11]*k2.w
                         + q1[12]*k3.x + q1[13]*k3.y + q1[14]*k3.z + q1[15]*k3.w;
                p0 += __shfl_xor_sync(0xffffffffu, p0, 1);
                p0 += __shfl_xor_sync(0xffffffffu, p0, 2);
                p1 += __shfl_xor_sync(0xffffffffu, p1, 1);
                p1 += __shfl_xor_sync(0xffffffffu, p1, 2);
                p0 *= 0.125f;
                p1 *= 0.125f;
                int kj = kb64 + j;
                if (kj > qg0) p0 = -1e30f;
                if (kj > qg1) p1 = -1e30f;
                s0[jj] = p0;
                s1[jj] = p1;
            }
            float mc0 = s0[0], mc1 = s1[0];
#pragma unroll
            for (int jj = 1; jj < 16; jj++) {
                mc0 = fmaxf(mc0, s0[jj]);
                mc1 = fmaxf(mc1, s1[jj]);
            }
            float mn0 = fmaxf(m0, mc0), mn1 = fmaxf(m1, mc1);
            float c0 = __expf(m0 - mn0), c1 = __expf(m1 - mn1);
            l0 *= c0; l1 *= c1;
#pragma unroll
            for (int d = 0; d < 16; d++) { a0[d] *= c0; a1[d] *= c1; }
#pragma unroll
            for (int jj = 0; jj < 16; jj++) {
                float p0 = __expf(s0[jj] - mn0);
                float p1 = __expf(s1[jj] - mn1);
                if (s0[jj] <= -1e29f) p0 = 0.f;
                if (s1[jj] <= -1e29f) p1 = 0.f;
                l0 += p0; l1 += p1;
                const float4* vr = (const float4*)&sV[(jc + jj) * 64 + t * 16];
                float4 v0 = vr[0], v1 = vr[1], v2 = vr[2], v3 = vr[3];
                a0[0] += p0*v0.x;  a0[1] += p0*v0.y;  a0[2] += p0*v0.z;  a0[3] += p0*v0.w;
                a0[4] += p0*v1.x;  a0[5] += p0*v1.y;  a0[6] += p0*v1.z;  a0[7] += p0*v1.w;
                a0[8] += p0*v2.x;  a0[9] += p0*v2.y;  a0[10]+= p0*v2.z;  a0[11]+= p0*v2.w;
                a0[12]+= p0*v3.x;  a0[13]+= p0*v3.y;  a0[14]+= p0*v3.z;  a0[15]+= p0*v3.w;
                a1[0] += p1*v0.x;  a1[1] += p1*v0.y;  a1[2] += p1*v0.z;  a1[3] += p1*v0.w;
                a1[4] += p1*v1.x;  a1[5] += p1*v1.y;  a1[6] += p1*v1.z;  a1[7] += p1*v1.w;
                a1[8] += p1*v2.x;  a1[9] += p1*v2.y;  a1[10]+= p1*v2.z;  a1[11]+= p1*v2.w;
                a1[12]+= p1*v3.x;  a1[13]+= p1*v3.y;  a1[14]+= p1*v3.z;  a1[15]+= p1*v3.w;
            }
            m0 = mn0; m1 = mn1;
        }
    }

    float inv0 = 1.f / l0, inv1 = 1.f / l1;
    float* Op0 = O + ((size_t)(b * SEQ_L + qg0) * DIM) + h * DHEAD + t * 16;
    float* Op1 = O + ((size_t)(b * SEQ_L + qg1) * DIM) + h * DHEAD + t * 16;
#pragma unroll
    for (int d = 0; d < 16; d++) {
        Op0[d] = a0[d] * inv0;
        Op1[d] = a1[d] * inv1;
    }
}

// ---------------------------------------------------------------------------
extern "C" void kernel_launch(void* const* d_in, const int* in_sizes, int n_in,
                              void* d_out, int out_size)
{
    const float* q  = (const float*)d_in[0];
    const float* k  = (const float*)d_in[1];
    const float* v  = (const float*)d_in[2];
    // d_in[3] = mask (causal triu) — applied analytically, not read
    const float* Wq = (const float*)d_in[4];
    const float* bq = (const float*)d_in[5];
    const float* Wk = (const float*)d_in[6];
    const float* bk = (const float*)d_in[7];
    const float* Wv = (const float*)d_in[8];
    const float* bv = (const float*)d_in[9];
    const float* Wo = (const float*)d_in[10];
    const float* bo = (const float*)d_in[11];

    float *gq, *gk, *gv, *go, *gwt;
    cudaGetSymbolAddress((void**)&gq, g_Q);
    cudaGetSymbolAddress((void**)&gk, g_K);
    cudaGetSymbolAddress((void**)&gv, g_V);
    cudaGetSymbolAddress((void**)&go, g_O);
    cudaGetSymbolAddress((void**)&gwt, g_Wt);

    static int configured = 0;
    if (!configured) {
        cudaFuncSetAttribute(attn_kernel, cudaFuncAttributeMaxDynamicSharedMemorySize, 65536);
        configured = 1;
    }

    const int M = BATCH * SEQ_L;   // 4096

    // Transpose all four weight matrices (K-major B tiles)
    transpose4<<<dim3(32, 32, 4), dim3(32, 8)>>>(Wq, Wk, Wv, Wo, gwt);

    dim3 ggrid(DIM / 128, M / 128);   // (8, 32)
    gemm_mma<<<ggrid, 256>>>(q, gwt + 0 * DIM * DIM, bq, gq, DIM, 1);
    gemm_mma<<<ggrid, 256>>>(k, gwt + 1 * DIM * DIM, bk, gk, DIM, 1);
    gemm_mma<<<ggrid, 256>>>(v, gwt + 2 * DIM * DIM, bv, gv, DIM, 1);

    attn_kernel<<<dim3(SEQ_L / 128, NHEAD, BATCH), 256, 65536>>>(gq, gk, gv, go);

    gemm_mma<<<ggrid, 256>>>(go, gwt + 3 * DIM * DIM, bo, (float*)d_out, DIM, 0);
}

// round 9
// speedup vs baseline: 4.7298x; 2.4630x over previous
#include <cuda_runtime.h>
#include <cstdint>

#define SEQ_L 2048
#define DIM 1024
#define NHEAD 16
#define DHEAD 64
#define BATCH 2

// Scratch (allocation-free)
__device__ float g_Q[BATCH * NHEAD * SEQ_L * DHEAD];
__device__ float g_K[BATCH * NHEAD * SEQ_L * DHEAD];
__device__ float g_Vt[BATCH * NHEAD * DHEAD * SEQ_L];  // V transposed: [B,H,DH,L]
__device__ float g_O[BATCH * SEQ_L * DIM];
__device__ float g_Wt[4 * DIM * DIM];   // transposed weights: Wt[n*K+k] = W[k*N+n]

// ---------------------------------------------------------------------------
__device__ __forceinline__ unsigned smem_u32(const void* p) {
    unsigned a;
    asm("{ .reg .u64 t; cvta.to.shared.u64 t, %1; cvt.u32.u64 %0, t; }"
        : "=r"(a) : "l"(p));
    return a;
}

__device__ __forceinline__ unsigned f2tf32(float f) {
    unsigned u;
    asm("cvt.rna.tf32.f32 %0, %1;" : "=r"(u) : "f"(f));
    return u;
}

__device__ __forceinline__ float uif(unsigned u) { return __uint_as_float(u); }

__device__ __forceinline__ void mma_tf32(float* c, const unsigned* a, const unsigned* b) {
    asm volatile(
        "mma.sync.aligned.m16n8k8.row.col.f32.tf32.tf32.f32 "
        "{%0,%1,%2,%3}, {%4,%5,%6,%7}, {%8,%9}, {%0,%1,%2,%3};"
        : "+f"(c[0]), "+f"(c[1]), "+f"(c[2]), "+f"(c[3])
        : "r"(a[0]), "r"(a[1]), "r"(a[2]), "r"(a[3]), "r"(b[0]), "r"(b[1]));
}

// ---------------------------------------------------------------------------
// Batched 1024x1024 transpose: g_Wt[z] = W_z^T
// ---------------------------------------------------------------------------
__global__ __launch_bounds__(256) void transpose4(
    const float* __restrict__ w0, const float* __restrict__ w1,
    const float* __restrict__ w2, const float* __restrict__ w3,
    float* __restrict__ out)
{
    __shared__ float tile[32][33];
    const float* in = (blockIdx.z == 0) ? w0 : (blockIdx.z == 1) ? w1
                    : (blockIdx.z == 2) ? w2 : w3;
    float* o = out + (size_t)blockIdx.z * DIM * DIM;
    const int x = blockIdx.x * 32;
    const int y = blockIdx.y * 32;
    const int tx = threadIdx.x, ty = threadIdx.y;
#pragma unroll
    for (int i = 0; i < 32; i += 8)
        tile[ty + i][tx] = in[(size_t)(y + ty + i) * DIM + x + tx];
    __syncthreads();
#pragma unroll
    for (int i = 0; i < 32; i += 8)
        o[(size_t)(x + ty + i) * DIM + y + tx] = tile[tx][ty + i];
}

// ---------------------------------------------------------------------------
// tf32 mma.sync GEMM: out = X[M,1024] @ Wt^T + bias   (Wt is [N,K], K-major)
// remap: 0 = row-major [M,N]; 1 = [B,H,L,DH]; 2 = [B,H,DH,L] (transposed V)
// ---------------------------------------------------------------------------
#define BK 16

__global__ __launch_bounds__(256) void gemm_mma(
    const float* __restrict__ X, const float* __restrict__ Wt,
    const float* __restrict__ bias, float* __restrict__ out,
    int Kdim, int remap)
{
    __shared__ __align__(16) float As[2][128][20];
    __shared__ __align__(16) float Bs[2][128][20];

    const int tid = threadIdx.x;
    const int wid = tid >> 5, lid = tid & 31;
    const int wm = wid >> 2;
    const int wn = wid & 3;
    const int gid = lid >> 2;
    const int tig = lid & 3;
    const int bm = blockIdx.y * 128;
    const int bn = blockIdx.x * 128;

    float acc[4][4][4];
#pragma unroll
    for (int mf = 0; mf < 4; mf++)
#pragma unroll
        for (int nf = 0; nf < 4; nf++)
#pragma unroll
            for (int r = 0; r < 4; r++) acc[mf][nf][r] = 0.f;

    const int ldrow0 = tid >> 2;
    const int ldk4 = (tid & 3) << 2;
    const int nchunk = Kdim / BK;

    {
#pragma unroll
        for (int i = 0; i < 2; i++) {
            int row = ldrow0 + i * 64;
            unsigned da = smem_u32(&As[0][row][ldk4]);
            unsigned db = smem_u32(&Bs[0][row][ldk4]);
            const float* sa = X + (size_t)(bm + row) * Kdim + ldk4;
            const float* sb = Wt + (size_t)(bn + row) * Kdim + ldk4;
            asm volatile("cp.async.ca.shared.global [%0], [%1], 16;" :: "r"(da), "l"(sa));
            asm volatile("cp.async.ca.shared.global [%0], [%1], 16;" :: "r"(db), "l"(sb));
        }
        asm volatile("cp.async.commit_group;");
    }

    for (int c = 0; c < nchunk; c++) {
        const int buf = c & 1;
        if (c + 1 < nchunk) {
            const int k0 = (c + 1) * BK;
            const int nb = buf ^ 1;
#pragma unroll
            for (int i = 0; i < 2; i++) {
                int row = ldrow0 + i * 64;
                unsigned da = smem_u32(&As[nb][row][ldk4]);
                unsigned db = smem_u32(&Bs[nb][row][ldk4]);
                const float* sa = X + (size_t)(bm + row) * Kdim + k0 + ldk4;
                const float* sb = Wt + (size_t)(bn + row) * Kdim + k0 + ldk4;
                asm volatile("cp.async.ca.shared.global [%0], [%1], 16;" :: "r"(da), "l"(sa));
                asm volatile("cp.async.ca.shared.global [%0], [%1], 16;" :: "r"(db), "l"(sb));
            }
            asm volatile("cp.async.commit_group;");
            asm volatile("cp.async.wait_group 1;");
        } else {
            asm volatile("cp.async.wait_group 0;");
        }
        __syncthreads();

#pragma unroll
        for (int ks = 0; ks < BK; ks += 8) {
            unsigned af[4][4], bf[4][2];
#pragma unroll
            for (int mf = 0; mf < 4; mf++) {
                int r0 = wm * 64 + mf * 16 + gid;
                af[mf][0] = f2tf32(As[buf][r0][ks + tig]);
                af[mf][1] = f2tf32(As[buf][r0 + 8][ks + tig]);
                af[mf][2] = f2tf32(As[buf][r0][ks + tig + 4]);
                af[mf][3] = f2tf32(As[buf][r0 + 8][ks + tig + 4]);
            }
#pragma unroll
            for (int nf = 0; nf < 4; nf++) {
                int r = wn * 32 + nf * 8 + gid;
                bf[nf][0] = f2tf32(Bs[buf][r][ks + tig]);
                bf[nf][1] = f2tf32(Bs[buf][r][ks + tig + 4]);
            }
#pragma unroll
            for (int mf = 0; mf < 4; mf++)
#pragma unroll
                for (int nf = 0; nf < 4; nf++)
                    mma_tf32(acc[mf][nf], af[mf], bf[nf]);
        }
        __syncthreads();
    }

    // ---- epilogue ----
#pragma unroll
    for (int mf = 0; mf < 4; mf++) {
#pragma unroll
        for (int nf = 0; nf < 4; nf++) {
            int row0 = bm + wm * 64 + mf * 16 + gid;
            int col = bn + wn * 32 + nf * 8 + 2 * tig;
            float b0 = bias[col], b1 = bias[col + 1];
            float2 vtop = make_float2(acc[mf][nf][0] + b0, acc[mf][nf][1] + b1);
            float2 vbot = make_float2(acc[mf][nf][2] + b0, acc[mf][nf][3] + b1);
            if (remap == 1) {
                int h = col >> 6;
                int dh = col & 63;
#pragma unroll
                for (int rr = 0; rr < 2; rr++) {
                    int row = row0 + rr * 8;
                    int b = row >> 11;
                    int l = row & (SEQ_L - 1);
                    size_t idx = ((((size_t)b * NHEAD + h) * SEQ_L + l) << 6) + dh;
                    *(float2*)&out[idx] = rr ? vbot : vtop;
                }
            } else if (remap == 2) {
                int h = col >> 6;
                int dh = col & 63;
#pragma unroll
                for (int rr = 0; rr < 2; rr++) {
                    int row = row0 + rr * 8;
                    int b = row >> 11;
                    int l = row & (SEQ_L - 1);
                    size_t base = (((size_t)b * NHEAD + h) * DHEAD + dh) * SEQ_L + l;
                    float2 v = rr ? vbot : vtop;
                    out[base] = v.x;
                    out[base + SEQ_L] = v.y;   // dh+1
                }
            } else {
                *(float2*)&out[(size_t)row0 * DIM + col] = vtop;
                *(float2*)&out[(size_t)(row0 + 8) * DIM + col] = vbot;
            }
        }
    }
}

// ---------------------------------------------------------------------------
// Tensor-core causal flash attention (tf32 mma.sync).
// Grid (L/128, H, B), 256 threads = 8 warps, each warp owns 16 q-rows.
// S = Q K^T via 3-pass tf32 split (fp32-accurate logits); softmax in log2
// domain in registers; P permuted to A-fragment layout via quad shuffles;
// O += P V via single-pass tf32. K/V double-buffered cp.async, XOR-swizzled.
// smem: 2 bufs x (K 64x64 + Vt 64x64) fp32 = 65536 B.
// ---------------------------------------------------------------------------
#define LOG2E_SCALE 0.1803368801111204f   // 0.125 * log2(e)

__global__ __launch_bounds__(256, 2) void attn_tc(
    const float* __restrict__ Q, const float* __restrict__ K,
    const float* __restrict__ Vt, float* __restrict__ O)
{
    extern __shared__ float sb[];   // [buf][ K:4096 | V:4096 ] floats

    const int qb = (gridDim.x - 1) - blockIdx.x;   // heavy CTAs first
    const int h = blockIdx.y;
    const int b = blockIdx.z;
    const int tid = threadIdx.x;
    const int w = tid >> 5, lid = tid & 31;
    const int g = lid >> 2, t = lid & 3;
    const int rowbase = qb * 128 + w * 16;

    const size_t qkOff = (size_t)(b * NHEAD + h) * SEQ_L * DHEAD;
    const size_t vtOff = (size_t)(b * NHEAD + h) * DHEAD * SEQ_L;

    // Q rows (rowbase+g, rowbase+g+8), cols ≡ t (mod 4), prescaled
    float qf0[16], qf1[16];
    {
        const float* Qr0 = Q + qkOff + (size_t)(rowbase + g) * DHEAD + t;
        const float* Qr1 = Qr0 + 8 * DHEAD;
#pragma unroll
        for (int i = 0; i < 16; i++) {
            qf0[i] = Qr0[4 * i] * LOG2E_SCALE;
            qf1[i] = Qr1[4 * i] * LOG2E_SCALE;
        }
    }

    float oacc[8][4];
#pragma unroll
    for (int nf = 0; nf < 8; nf++)
#pragma unroll
        for (int r = 0; r < 4; r++) oacc[nf][r] = 0.f;
    float m0 = -1e30f, m1 = -1e30f, l0 = 0.f, l1 = 0.f;

    const int nkb = 2 * qb + 2;

#define LOAD_BLOCK(kb_, buf_) do {                                            \
    float* dK = sb + (buf_) * 8192;                                           \
    float* dV = dK + 4096;                                                    \
    const float* gK = K + qkOff + (size_t)((kb_) * 64) * 64;                  \
    const float* gV = Vt + vtOff + (kb_) * 64;                                \
    _Pragma("unroll")                                                         \
    for (int r_ = 0; r_ < 4; r_++) {                                          \
        int idx = tid + r_ * 256;                                             \
        int row = idx >> 4;                                                   \
        int c4 = (idx & 15) << 2;                                             \
        int sw = (row << 6) + (c4 ^ ((row & 7) << 2));                        \
        unsigned dk = smem_u32(dK + sw);                                      \
        const float* sk = gK + row * 64 + c4;                                 \
        asm volatile("cp.async.ca.shared.global [%0], [%1], 16;" :: "r"(dk), "l"(sk)); \
        unsigned dv = smem_u32(dV + sw);                                      \
        const float* sv = gV + (size_t)row * SEQ_L + c4;                      \
        asm volatile("cp.async.ca.shared.global [%0], [%1], 16;" :: "r"(dv), "l"(sv)); \
    }                                                                         \
    asm volatile("cp.async.commit_group;");                                   \
} while (0)

    LOAD_BLOCK(0, 0);

    for (int kb = 0; kb < nkb; kb++) {
        const int buf = kb & 1;
        if (kb + 1 < nkb) {
            LOAD_BLOCK(kb + 1, buf ^ 1);
            asm volatile("cp.async.wait_group 1;");
        } else {
            asm volatile("cp.async.wait_group 0;");
        }
        __syncthreads();

        const int kv0 = kb * 64;
        const bool active = (kv0 <= rowbase + 15);
        if (active) {
            const float* sK_ = sb + buf * 8192;
            const float* sV_ = sK_ + 4096;

            // ---- S = Q K^T (3-pass tf32 split) ----
            float sacc[8][4];
#pragma unroll
            for (int nf = 0; nf < 8; nf++)
#pragma unroll
                for (int r = 0; r < 4; r++) sacc[nf][r] = 0.f;

#pragma unroll
            for (int ks = 0; ks < 8; ks++) {
                unsigned qh[4], ql[4];
                qh[0] = f2tf32(qf0[2*ks]);     ql[0] = f2tf32(qf0[2*ks]     - uif(qh[0]));
                qh[1] = f2tf32(qf1[2*ks]);     ql[1] = f2tf32(qf1[2*ks]     - uif(qh[1]));
                qh[2] = f2tf32(qf0[2*ks + 1]); ql[2] = f2tf32(qf0[2*ks + 1] - uif(qh[2]));
                qh[3] = f2tf32(qf1[2*ks + 1]); ql[3] = f2tf32(qf1[2*ks + 1] - uif(qh[3]));
#pragma unroll
                for (int nf = 0; nf < 8; nf++) {
                    int nrow = nf * 8 + g;
                    float b0f = sK_[(nrow << 6) + (((ks << 3) + t)     ^ (g << 2))];
                    float b1f = sK_[(nrow << 6) + (((ks << 3) + t + 4) ^ (g << 2))];
                    unsigned bh[2], bl[2];
                    bh[0] = f2tf32(b0f); bl[0] = f2tf32(b0f - uif(bh[0]));
                    bh[1] = f2tf32(b1f); bl[1] = f2tf32(b1f - uif(bh[1]));
                    mma_tf32(sacc[nf], qh, bh);
                    mma_tf32(sacc[nf], ql, bh);
                    mma_tf32(sacc[nf], qh, bl);
                }
            }

            // ---- causal mask (only near diagonal) ----
            if (kv0 + 63 > rowbase) {
#pragma unroll
                for (int nf = 0; nf < 8; nf++)
#pragma unroll
                    for (int r = 0; r < 4; r++) {
                        int col = kv0 + nf * 8 + 2 * t + (r & 1);
                        int row = rowbase + g + ((r >> 1) << 3);
                        if (col > row) sacc[nf][r] = -1e30f;
                    }
            }

            // ---- online softmax (log2 domain) ----
            float mx0 = -1e30f, mx1 = -1e30f;
#pragma unroll
            for (int nf = 0; nf < 8; nf++) {
                mx0 = fmaxf(mx0, fmaxf(sacc[nf][0], sacc[nf][1]));
                mx1 = fmaxf(mx1, fmaxf(sacc[nf][2], sacc[nf][3]));
            }
            mx0 = fmaxf(mx0, __shfl_xor_sync(0xffffffffu, mx0, 1));
            mx0 = fmaxf(mx0, __shfl_xor_sync(0xffffffffu, mx0, 2));
            mx1 = fmaxf(mx1, __shfl_xor_sync(0xffffffffu, mx1, 1));
            mx1 = fmaxf(mx1, __shfl_xor_sync(0xffffffffu, mx1, 2));
            float mn0 = fmaxf(m0, mx0), mn1 = fmaxf(m1, mx1);
            float c0 = exp2f(m0 - mn0), c1 = exp2f(m1 - mn1);
            m0 = mn0; m1 = mn1;

            float s0 = 0.f, s1 = 0.f;
#pragma unroll
            for (int nf = 0; nf < 8; nf++) {
                float p0 = exp2f(sacc[nf][0] - mn0);
                float p1 = exp2f(sacc[nf][1] - mn0);
                float p2 = exp2f(sacc[nf][2] - mn1);
                float p3 = exp2f(sacc[nf][3] - mn1);
                s0 += p0 + p1; s1 += p2 + p3;
                sacc[nf][0] = p0; sacc[nf][1] = p1;
                sacc[nf][2] = p2; sacc[nf][3] = p3;
            }
            s0 += __shfl_xor_sync(0xffffffffu, s0, 1);
            s0 += __shfl_xor_sync(0xffffffffu, s0, 2);
            s1 += __shfl_xor_sync(0xffffffffu, s1, 1);
            s1 += __shfl_xor_sync(0xffffffffu, s1, 2);
            l0 = l0 * c0 + s0;
            l1 = l1 * c1 + s1;
#pragma unroll
            for (int nf = 0; nf < 8; nf++) {
                oacc[nf][0] *= c0; oacc[nf][1] *= c0;
                oacc[nf][2] *= c1; oacc[nf][3] *= c1;
            }

            // ---- O += P V  (P: C-layout -> A-layout via quad shuffles) ----
            const int srcA = (lid & 28) | (t >> 1);
            const int srcB = srcA + 2;
            const bool odd = (t & 1);
#pragma unroll
            for (int f = 0; f < 8; f++) {
                float v0a = __shfl_sync(0xffffffffu, sacc[f][0], srcA);
                float v1a = __shfl_sync(0xffffffffu, sacc[f][1], srcA);
                float v2a = __shfl_sync(0xffffffffu, sacc[f][2], srcA);
                float v3a = __shfl_sync(0xffffffffu, sacc[f][3], srcA);
                float v0b = __shfl_sync(0xffffffffu, sacc[f][0], srcB);
                float v1b = __shfl_sync(0xffffffffu, sacc[f][1], srcB);
                float v2b = __shfl_sync(0xffffffffu, sacc[f][2], srcB);
                float v3b = __shfl_sync(0xffffffffu, sacc[f][3], srcB);
                unsigned pa[4];
                pa[0] = f2tf32(odd ? v1a : v0a);   // (g,    f*8+t)
                pa[1] = f2tf32(odd ? v3a : v2a);   // (g+8,  f*8+t)
                pa[2] = f2tf32(odd ? v1b : v0b);   // (g,    f*8+t+4)
                pa[3] = f2tf32(odd ? v3b : v2b);   // (g+8,  f*8+t+4)
#pragma unroll
                for (int nf = 0; nf < 8; nf++) {
                    int nrow = nf * 8 + g;
                    float b0f = sV_[(nrow << 6) + (((f << 3) + t)     ^ (g << 2))];
                    float b1f = sV_[(nrow << 6) + (((f << 3) + t + 4) ^ (g << 2))];
                    unsigned vb[2] = { f2tf32(b0f), f2tf32(b1f) };
                    mma_tf32(oacc[nf], pa, vb);
                }
            }
        }
        __syncthreads();
    }

    // ---- write O [B, L, D] ----
    float inv0 = 1.f / l0, inv1 = 1.f / l1;
    int row0 = rowbase + g;
    float* O0 = O + ((size_t)b * SEQ_L + row0) * DIM + h * DHEAD;
    float* O1 = O0 + (size_t)8 * DIM;
#pragma unroll
    for (int nf = 0; nf < 8; nf++) {
        int col = nf * 8 + 2 * t;
        *(float2*)&O0[col] = make_float2(oacc[nf][0] * inv0, oacc[nf][1] * inv0);
        *(float2*)&O1[col] = make_float2(oacc[nf][2] * inv1, oacc[nf][3] * inv1);
    }
}

// ---------------------------------------------------------------------------
extern "C" void kernel_launch(void* const* d_in, const int* in_sizes, int n_in,
                              void* d_out, int out_size)
{
    const float* q  = (const float*)d_in[0];
    const float* k  = (const float*)d_in[1];
    const float* v  = (const float*)d_in[2];
    // d_in[3] = mask (causal triu) — applied analytically, not read
    const float* Wq = (const float*)d_in[4];
    const float* bq = (const float*)d_in[5];
    const float* Wk = (const float*)d_in[6];
    const float* bk = (const float*)d_in[7];
    const float* Wv = (const float*)d_in[8];
    const float* bv = (const float*)d_in[9];
    const float* Wo = (const float*)d_in[10];
    const float* bo = (const float*)d_in[11];

    float *gq, *gk, *gvt, *go, *gwt;
    cudaGetSymbolAddress((void**)&gq, g_Q);
    cudaGetSymbolAddress((void**)&gk, g_K);
    cudaGetSymbolAddress((void**)&gvt, g_Vt);
    cudaGetSymbolAddress((void**)&go, g_O);
    cudaGetSymbolAddress((void**)&gwt, g_Wt);

    static int configured = 0;
    if (!configured) {
        cudaFuncSetAttribute(attn_tc, cudaFuncAttributeMaxDynamicSharedMemorySize, 65536);
        configured = 1;
    }

    const int M = BATCH * SEQ_L;   // 4096

    transpose4<<<dim3(32, 32, 4), dim3(32, 8)>>>(Wq, Wk, Wv, Wo, gwt);

    dim3 ggrid(DIM / 128, M / 128);   // (8, 32)
    gemm_mma<<<ggrid, 256>>>(q, gwt + 0 * DIM * DIM, bq, gq, DIM, 1);
    gemm_mma<<<ggrid, 256>>>(k, gwt + 1 * DIM * DIM, bk, gk, DIM, 1);
    gemm_mma<<<ggrid, 256>>>(v, gwt + 2 * DIM * DIM, bv, gvt, DIM, 2);

    attn_tc<<<dim3(SEQ_L / 128, NHEAD, BATCH), 256, 65536>>>(gq, gk, gvt, go);

    gemm_mma<<<ggrid, 256>>>(go, gwt + 3 * DIM * DIM, bo, (float*)d_out, DIM, 0);
}

// round 10
// speedup vs baseline: 5.8965x; 1.2467x over previous
#include <cuda_runtime.h>
#include <cstdint>

#define SEQ_L 2048
#define DIM 1024
#define NHEAD 16
#define DHEAD 64
#define BATCH 2

// Scratch (allocation-free)
__device__ float g_Q[BATCH * NHEAD * SEQ_L * DHEAD];
__device__ float g_Khi[BATCH * NHEAD * SEQ_L * DHEAD];
__device__ float g_Klo[BATCH * NHEAD * SEQ_L * DHEAD];
__device__ float g_Vt[BATCH * NHEAD * DHEAD * SEQ_L];  // V^T: [B,H,DH,L], tf32-rounded
__device__ float g_O[BATCH * SEQ_L * DIM];
__device__ float g_Wt[4 * DIM * DIM];   // transposed weights, tf32-rounded

// ---------------------------------------------------------------------------
__device__ __forceinline__ unsigned smem_u32(const void* p) {
    unsigned a;
    asm("{ .reg .u64 t; cvta.to.shared.u64 t, %1; cvt.u32.u64 %0, t; }"
        : "=r"(a) : "l"(p));
    return a;
}

__device__ __forceinline__ unsigned f2tf32(float f) {
    unsigned u;
    asm("cvt.rna.tf32.f32 %0, %1;" : "=r"(u) : "f"(f));
    return u;
}

__device__ __forceinline__ float uif(unsigned u) { return __uint_as_float(u); }
__device__ __forceinline__ unsigned fau(float f) { return __float_as_uint(f); }

__device__ __forceinline__ void mma_tf32(float* c, const unsigned* a, const unsigned* b) {
    asm volatile(
        "mma.sync.aligned.m16n8k8.row.col.f32.tf32.tf32.f32 "
        "{%0,%1,%2,%3}, {%4,%5,%6,%7}, {%8,%9}, {%0,%1,%2,%3};"
        : "+f"(c[0]), "+f"(c[1]), "+f"(c[2]), "+f"(c[3])
        : "r"(a[0]), "r"(a[1]), "r"(a[2]), "r"(a[3]), "r"(b[0]), "r"(b[1]));
}

// ---------------------------------------------------------------------------
// Batched transpose + tf32 pre-round: g_Wt[z] = round_tf32(W_z^T)
// ---------------------------------------------------------------------------
__global__ __launch_bounds__(256) void transpose4(
    const float* __restrict__ w0, const float* __restrict__ w1,
    const float* __restrict__ w2, const float* __restrict__ w3,
    float* __restrict__ out)
{
    __shared__ float tile[32][33];
    const float* in = (blockIdx.z == 0) ? w0 : (blockIdx.z == 1) ? w1
                    : (blockIdx.z == 2) ? w2 : w3;
    float* o = out + (size_t)blockIdx.z * DIM * DIM;
    const int x = blockIdx.x * 32;
    const int y = blockIdx.y * 32;
    const int tx = threadIdx.x, ty = threadIdx.y;
#pragma unroll
    for (int i = 0; i < 32; i += 8)
        tile[ty + i][tx] = in[(size_t)(y + ty + i) * DIM + x + tx];
    __syncthreads();
#pragma unroll
    for (int i = 0; i < 32; i += 8)
        o[(size_t)(x + ty + i) * DIM + y + tx] = uif(f2tf32(tile[tx][ty + i]));
}

// ---------------------------------------------------------------------------
// tf32 mma.sync GEMM: out = X[M,1024] @ Wt^T + bias   (Wt [N,K] K-major,
// PRE-ROUNDED to tf32 -> B fragments load raw bits).
// CTA 128x128, BK=32, 128 threads = 4 warps of 64x64 tiles.
// remap: 0 = row-major [M,N]; 1 = [B,H,L,DH]; 2 = [B,H,DH,L] tf32-rounded;
//        3 = [B,H,L,DH] hi/lo tf32 split (out = hi, out2 = lo)
// ---------------------------------------------------------------------------
#define BK 32
#define GSMEM (2 * 2 * 128 * 36 * 4)   // 73728 bytes

__global__ __launch_bounds__(128) void gemm_mma(
    const float* __restrict__ X, const float* __restrict__ Wt,
    const float* __restrict__ bias, float* __restrict__ out,
    float* __restrict__ out2, int Kdim, int remap)
{
    extern __shared__ float gsm[];
    float (*As)[128][36] = (float (*)[128][36])gsm;
    float (*Bs)[128][36] = (float (*)[128][36])(gsm + 2 * 128 * 36);

    const int tid = threadIdx.x;
    const int wid = tid >> 5, lid = tid & 31;
    const int wm = wid >> 1;
    const int wn = wid & 1;
    const int g = lid >> 2;
    const int t = lid & 3;
    const int bm = blockIdx.y * 128;
    const int bn = blockIdx.x * 128;

    float acc[4][8][4];
#pragma unroll
    for (int mf = 0; mf < 4; mf++)
#pragma unroll
        for (int nf = 0; nf < 8; nf++)
#pragma unroll
            for (int r = 0; r < 4; r++) acc[mf][nf][r] = 0.f;

    const int nchunk = Kdim / BK;   // 32

    // per-thread staging: 8 float4 per tile (128 rows x 32 cols, 128 threads)
#define STAGE(buf_, k0_) do {                                                 \
    _Pragma("unroll")                                                         \
    for (int i_ = 0; i_ < 8; i_++) {                                          \
        int idx = tid + i_ * 128;                                             \
        int row = idx >> 3;                                                   \
        int c4 = (idx & 7) << 2;                                              \
        unsigned da = smem_u32(&As[buf_][row][c4]);                           \
        unsigned db = smem_u32(&Bs[buf_][row][c4]);                           \
        const float* sa = X + (size_t)(bm + row) * Kdim + (k0_) + c4;         \
        const float* sb = Wt + (size_t)(bn + row) * Kdim + (k0_) + c4;        \
        asm volatile("cp.async.ca.shared.global [%0], [%1], 16;" :: "r"(da), "l"(sa)); \
        asm volatile("cp.async.ca.shared.global [%0], [%1], 16;" :: "r"(db), "l"(sb)); \
    }                                                                         \
    asm volatile("cp.async.commit_group;");                                   \
} while (0)

    STAGE(0, 0);

    for (int c = 0; c < nchunk; c++) {
        const int buf = c & 1;
        if (c + 1 < nchunk) {
            STAGE(buf ^ 1, (c + 1) * BK);
            asm volatile("cp.async.wait_group 1;");
        } else {
            asm volatile("cp.async.wait_group 0;");
        }
        __syncthreads();

#pragma unroll
        for (int ks = 0; ks < BK; ks += 8) {
            unsigned af[4][4], bf[8][2];
#pragma unroll
            for (int mf = 0; mf < 4; mf++) {
                int r0 = wm * 64 + mf * 16 + g;
                af[mf][0] = f2tf32(As[buf][r0][ks + t]);
                af[mf][1] = f2tf32(As[buf][r0 + 8][ks + t]);
                af[mf][2] = f2tf32(As[buf][r0][ks + t + 4]);
                af[mf][3] = f2tf32(As[buf][r0 + 8][ks + t + 4]);
            }
#pragma unroll
            for (int nf = 0; nf < 8; nf++) {
                int r = wn * 64 + nf * 8 + g;
                bf[nf][0] = fau(Bs[buf][r][ks + t]);       // pre-rounded
                bf[nf][1] = fau(Bs[buf][r][ks + t + 4]);
            }
#pragma unroll
            for (int mf = 0; mf < 4; mf++)
#pragma unroll
                for (int nf = 0; nf < 8; nf++)
                    mma_tf32(acc[mf][nf], af[mf], bf[nf]);
        }
        __syncthreads();
    }

    // ---- epilogue ----
#pragma unroll
    for (int mf = 0; mf < 4; mf++) {
#pragma unroll
        for (int nf = 0; nf < 8; nf++) {
            int row0 = bm + wm * 64 + mf * 16 + g;
            int col = bn + wn * 64 + nf * 8 + 2 * t;
            float b0 = bias[col], b1 = bias[col + 1];
            float2 vtop = make_float2(acc[mf][nf][0] + b0, acc[mf][nf][1] + b1);
            float2 vbot = make_float2(acc[mf][nf][2] + b0, acc[mf][nf][3] + b1);
            if (remap == 0) {
                *(float2*)&out[(size_t)row0 * DIM + col] = vtop;
                *(float2*)&out[(size_t)(row0 + 8) * DIM + col] = vbot;
            } else {
                int h = col >> 6;
                int dh = col & 63;
#pragma unroll
                for (int rr = 0; rr < 2; rr++) {
                    int row = row0 + rr * 8;
                    int b = row >> 11;
                    int l = row & (SEQ_L - 1);
                    float2 v = rr ? vbot : vtop;
                    if (remap == 1) {
                        size_t idx = ((((size_t)b * NHEAD + h) * SEQ_L + l) << 6) + dh;
                        *(float2*)&out[idx] = v;
                    } else if (remap == 2) {
                        size_t base = (((size_t)b * NHEAD + h) * DHEAD + dh) * SEQ_L + l;
                        out[base] = uif(f2tf32(v.x));
                        out[base + SEQ_L] = uif(f2tf32(v.y));
                    } else {   // remap == 3: hi/lo tf32 split
                        size_t idx = ((((size_t)b * NHEAD + h) * SEQ_L + l) << 6) + dh;
                        float h0 = uif(f2tf32(v.x)), h1 = uif(f2tf32(v.y));
                        *(float2*)&out[idx] = make_float2(h0, h1);
                        *(float2*)&out2[idx] =
                            make_float2(uif(f2tf32(v.x - h0)), uif(f2tf32(v.y - h1)));
                    }
                }
            }
        }
    }
}

// ---------------------------------------------------------------------------
// Tensor-core causal flash attention (tf32 mma.sync), pre-split K.
// Grid (L/128, H, B), 256 threads = 8 warps x 16 q-rows.
// smem: 2 bufs x (Khi 16KB | Klo 16KB | V 16KB) = 98304 B.
// ---------------------------------------------------------------------------
#define LOG2E_SCALE 0.1803368801111204f   // 0.125 * log2(e)

__global__ __launch_bounds__(256, 2) void attn_tc(
    const float* __restrict__ Q, const float* __restrict__ Khi,
    const float* __restrict__ Klo, const float* __restrict__ Vt,
    float* __restrict__ O)
{
    extern __shared__ float sb[];   // [buf][ Khi:4096 | Klo:4096 | V:4096 ]

    const int qb = (gridDim.x - 1) - blockIdx.x;   // heavy CTAs first
    const int h = blockIdx.y;
    const int b = blockIdx.z;
    const int tid = threadIdx.x;
    const int w = tid >> 5, lid = tid & 31;
    const int g = lid >> 2, t = lid & 3;
    const int rowbase = qb * 128 + w * 16;

    const size_t qkOff = (size_t)(b * NHEAD + h) * SEQ_L * DHEAD;
    const size_t vtOff = (size_t)(b * NHEAD + h) * DHEAD * SEQ_L;

    // Q rows (rowbase+g, rowbase+g+8), cols ≡ t (mod 4), prescaled
    float qf0[16], qf1[16];
    {
        const float* Qr0 = Q + qkOff + (size_t)(rowbase + g) * DHEAD + t;
        const float* Qr1 = Qr0 + 8 * DHEAD;
#pragma unroll
        for (int i = 0; i < 16; i++) {
            qf0[i] = Qr0[4 * i] * LOG2E_SCALE;
            qf1[i] = Qr1[4 * i] * LOG2E_SCALE;
        }
    }

    float oacc[8][4];
#pragma unroll
    for (int nf = 0; nf < 8; nf++)
#pragma unroll
        for (int r = 0; r < 4; r++) oacc[nf][r] = 0.f;
    float m0 = -1e30f, m1 = -1e30f, l0 = 0.f, l1 = 0.f;

    const int nkb = 2 * qb + 2;

#define LOAD_BLOCK(kb_, buf_) do {                                            \
    float* dKh = sb + (buf_) * 12288;                                         \
    float* dKl = dKh + 4096;                                                  \
    float* dV = dKh + 8192;                                                   \
    const float* gKh = Khi + qkOff + (size_t)((kb_) * 64) * 64;               \
    const float* gKl = Klo + qkOff + (size_t)((kb_) * 64) * 64;               \
    const float* gV = Vt + vtOff + (kb_) * 64;                                \
    _Pragma("unroll")                                                         \
    for (int r_ = 0; r_ < 4; r_++) {                                          \
        int idx = tid + r_ * 256;                                             \
        int row = idx >> 4;                                                   \
        int c4 = (idx & 15) << 2;                                             \
        int sw = (row << 6) + (c4 ^ ((row & 7) << 2));                        \
        unsigned dh_ = smem_u32(dKh + sw);                                    \
        const float* skh = gKh + row * 64 + c4;                               \
        asm volatile("cp.async.ca.shared.global [%0], [%1], 16;" :: "r"(dh_), "l"(skh)); \
        unsigned dl_ = smem_u32(dKl + sw);                                    \
        const float* skl = gKl + row * 64 + c4;                               \
        asm volatile("cp.async.ca.shared.global [%0], [%1], 16;" :: "r"(dl_), "l"(skl)); \
        unsigned dv_ = smem_u32(dV + sw);                                     \
        const float* sv = gV + (size_t)row * SEQ_L + c4;                      \
        asm volatile("cp.async.ca.shared.global [%0], [%1], 16;" :: "r"(dv_), "l"(sv)); \
    }                                                                         \
    asm volatile("cp.async.commit_group;");                                   \
} while (0)

    LOAD_BLOCK(0, 0);

    for (int kb = 0; kb < nkb; kb++) {
        const int buf = kb & 1;
        if (kb + 1 < nkb) {
            LOAD_BLOCK(kb + 1, buf ^ 1);
            asm volatile("cp.async.wait_group 1;");
        } else {
            asm volatile("cp.async.wait_group 0;");
        }
        __syncthreads();

        const int kv0 = kb * 64;
        const bool active = (kv0 <= rowbase + 15);
        if (active) {
            const float* sKh_ = sb + buf * 12288;
            const float* sKl_ = sKh_ + 4096;
            const float* sV_ = sKh_ + 8192;

            // ---- S = Q K^T (3-pass tf32 split; K pre-split in gmem) ----
            float sacc[8][4];
#pragma unroll
            for (int nf = 0; nf < 8; nf++)
#pragma unroll
                for (int r = 0; r < 4; r++) sacc[nf][r] = 0.f;

#pragma unroll
            for (int ks = 0; ks < 8; ks++) {
                unsigned qh[4], ql[4];
                qh[0] = f2tf32(qf0[2*ks]);     ql[0] = f2tf32(qf0[2*ks]     - uif(qh[0]));
                qh[1] = f2tf32(qf1[2*ks]);     ql[1] = f2tf32(qf1[2*ks]     - uif(qh[1]));
                qh[2] = f2tf32(qf0[2*ks + 1]); ql[2] = f2tf32(qf0[2*ks + 1] - uif(qh[2]));
                qh[3] = f2tf32(qf1[2*ks + 1]); ql[3] = f2tf32(qf1[2*ks + 1] - uif(qh[3]));
#pragma unroll
                for (int nf = 0; nf < 8; nf++) {
                    int base = (nf * 8 + g) << 6;
                    int c0 = ((ks << 3) + t) ^ (g << 2);
                    int c1 = ((ks << 3) + t + 4) ^ (g << 2);
                    unsigned bh[2] = { fau(sKh_[base + c0]), fau(sKh_[base + c1]) };
                    unsigned bl[2] = { fau(sKl_[base + c0]), fau(sKl_[base + c1]) };
                    mma_tf32(sacc[nf], qh, bh);
                    mma_tf32(sacc[nf], ql, bh);
                    mma_tf32(sacc[nf], qh, bl);
                }
            }

            // ---- causal mask (only near diagonal) ----
            if (kv0 + 63 > rowbase) {
#pragma unroll
                for (int nf = 0; nf < 8; nf++)
#pragma unroll
                    for (int r = 0; r < 4; r++) {
                        int col = kv0 + nf * 8 + 2 * t + (r & 1);
                        int row = rowbase + g + ((r >> 1) << 3);
                        if (col > row) sacc[nf][r] = -1e30f;
                    }
            }

            // ---- online softmax (log2 domain) ----
            float mx0 = -1e30f, mx1 = -1e30f;
#pragma unroll
            for (int nf = 0; nf < 8; nf++) {
                mx0 = fmaxf(mx0, fmaxf(sacc[nf][0], sacc[nf][1]));
                mx1 = fmaxf(mx1, fmaxf(sacc[nf][2], sacc[nf][3]));
            }
            mx0 = fmaxf(mx0, __shfl_xor_sync(0xffffffffu, mx0, 1));
            mx0 = fmaxf(mx0, __shfl_xor_sync(0xffffffffu, mx0, 2));
            mx1 = fmaxf(mx1, __shfl_xor_sync(0xffffffffu, mx1, 1));
            mx1 = fmaxf(mx1, __shfl_xor_sync(0xffffffffu, mx1, 2));
            float mn0 = fmaxf(m0, mx0), mn1 = fmaxf(m1, mx1);
            float c0 = exp2f(m0 - mn0), c1 = exp2f(m1 - mn1);
            m0 = mn0; m1 = mn1;

            float s0 = 0.f, s1 = 0.f;
#pragma unroll
            for (int nf = 0; nf < 8; nf++) {
                float p0 = exp2f(sacc[nf][0] - mn0);
                float p1 = exp2f(sacc[nf][1] - mn0);
                float p2 = exp2f(sacc[nf][2] - mn1);
                float p3 = exp2f(sacc[nf][3] - mn1);
                s0 += p0 + p1; s1 += p2 + p3;
                sacc[nf][0] = p0; sacc[nf][1] = p1;
                sacc[nf][2] = p2; sacc[nf][3] = p3;
            }
            s0 += __shfl_xor_sync(0xffffffffu, s0, 1);
            s0 += __shfl_xor_sync(0xffffffffu, s0, 2);
            s1 += __shfl_xor_sync(0xffffffffu, s1, 1);
            s1 += __shfl_xor_sync(0xffffffffu, s1, 2);
            l0 = l0 * c0 + s0;
            l1 = l1 * c1 + s1;
#pragma unroll
            for (int nf = 0; nf < 8; nf++) {
                oacc[nf][0] *= c0; oacc[nf][1] *= c0;
                oacc[nf][2] *= c1; oacc[nf][3] *= c1;
            }

            // ---- O += P V  (P: C-layout -> A-layout via quad shuffles) ----
            const int srcA = (lid & 28) | (t >> 1);
            const int srcB = srcA + 2;
            const bool odd = (t & 1);
#pragma unroll
            for (int f = 0; f < 8; f++) {
                float v0a = __shfl_sync(0xffffffffu, sacc[f][0], srcA);
                float v1a = __shfl_sync(0xffffffffu, sacc[f][1], srcA);
                float v2a = __shfl_sync(0xffffffffu, sacc[f][2], srcA);
                float v3a = __shfl_sync(0xffffffffu, sacc[f][3], srcA);
                float v0b = __shfl_sync(0xffffffffu, sacc[f][0], srcB);
                float v1b = __shfl_sync(0xffffffffu, sacc[f][1], srcB);
                float v2b = __shfl_sync(0xffffffffu, sacc[f][2], srcB);
                float v3b = __shfl_sync(0xffffffffu, sacc[f][3], srcB);
                unsigned pa[4];
                pa[0] = f2tf32(odd ? v1a : v0a);
                pa[1] = f2tf32(odd ? v3a : v2a);
                pa[2] = f2tf32(odd ? v1b : v0b);
                pa[3] = f2tf32(odd ? v3b : v2b);
#pragma unroll
                for (int nf = 0; nf < 8; nf++) {
                    int base = (nf * 8 + g) << 6;
                    unsigned vb[2] = {
                        fau(sV_[base + (((f << 3) + t) ^ (g << 2))]),
                        fau(sV_[base + (((f << 3) + t + 4) ^ (g << 2))]) };
                    mma_tf32(oacc[nf], pa, vb);
                }
            }
        }
        __syncthreads();
    }

    // ---- write O [B, L, D] ----
    float inv0 = 1.f / l0, inv1 = 1.f / l1;
    int row0 = rowbase + g;
    float* O0 = O + ((size_t)b * SEQ_L + row0) * DIM + h * DHEAD;
    float* O1 = O0 + (size_t)8 * DIM;
#pragma unroll
    for (int nf = 0; nf < 8; nf++) {
        int col = nf * 8 + 2 * t;
        *(float2*)&O0[col] = make_float2(oacc[nf][0] * inv0, oacc[nf][1] * inv0);
        *(float2*)&O1[col] = make_float2(oacc[nf][2] * inv1, oacc[nf][3] * inv1);
    }
}

// ---------------------------------------------------------------------------
extern "C" void kernel_launch(void* const* d_in, const int* in_sizes, int n_in,
                              void* d_out, int out_size)
{
    const float* q  = (const float*)d_in[0];
    const float* k  = (const float*)d_in[1];
    const float* v  = (const float*)d_in[2];
    // d_in[3] = mask (causal triu) — applied analytically, not read
    const float* Wq = (const float*)d_in[4];
    const float* bq = (const float*)d_in[5];
    const float* Wk = (const float*)d_in[6];
    const float* bk = (const float*)d_in[7];
    const float* Wv = (const float*)d_in[8];
    const float* bv = (const float*)d_in[9];
    const float* Wo = (const float*)d_in[10];
    const float* bo = (const float*)d_in[11];

    float *gq, *gkh, *gkl, *gvt, *go, *gwt;
    cudaGetSymbolAddress((void**)&gq, g_Q);
    cudaGetSymbolAddress((void**)&gkh, g_Khi);
    cudaGetSymbolAddress((void**)&gkl, g_Klo);
    cudaGetSymbolAddress((void**)&gvt, g_Vt);
    cudaGetSymbolAddress((void**)&go, g_O);
    cudaGetSymbolAddress((void**)&gwt, g_Wt);

    static int configured = 0;
    if (!configured) {
        cudaFuncSetAttribute(gemm_mma, cudaFuncAttributeMaxDynamicSharedMemorySize, GSMEM);
        cudaFuncSetAttribute(attn_tc, cudaFuncAttributeMaxDynamicSharedMemorySize, 98304);
        configured = 1;
    }

    const int M = BATCH * SEQ_L;   // 4096

    transpose4<<<dim3(32, 32, 4), dim3(32, 8)>>>(Wq, Wk, Wv, Wo, gwt);

    dim3 ggrid(DIM / 128, M / 128);   // (8, 32)
    gemm_mma<<<ggrid, 128, GSMEM>>>(q, gwt + 0 * DIM * DIM, bq, gq, nullptr, DIM, 1);
    gemm_mma<<<ggrid, 128, GSMEM>>>(k, gwt + 1 * DIM * DIM, bk, gkh, gkl, DIM, 3);
    gemm_mma<<<ggrid, 128, GSMEM>>>(v, gwt + 2 * DIM * DIM, bv, gvt, nullptr, DIM, 2);

    attn_tc<<<dim3(SEQ_L / 128, NHEAD, BATCH), 256, 98304>>>(gq, gkh, gkl, gvt, go);

    gemm_mma<<<ggrid, 128, GSMEM>>>(go, gwt + 3 * DIM * DIM, bo, (float*)d_out, nullptr, DIM, 0);
}

// round 11
// speedup vs baseline: 6.3173x; 1.0714x over previous
#include <cuda_runtime.h>
#include <cstdint>

#define SEQ_L 2048
#define DIM 1024
#define NHEAD 16
#define DHEAD 64
#define BATCH 2

// Scratch (allocation-free)
__device__ float g_Xr[3 * BATCH * SEQ_L * DIM];        // tf32-rounded q,k,v inputs
__device__ float g_Q[BATCH * NHEAD * SEQ_L * DHEAD];
__device__ float g_Khi[BATCH * NHEAD * SEQ_L * DHEAD];
__device__ float g_Klo[BATCH * NHEAD * SEQ_L * DHEAD];
__device__ float g_Vt[BATCH * NHEAD * DHEAD * SEQ_L]; // V^T [B,H,DH,L], tf32-rounded
__device__ float g_O[BATCH * SEQ_L * DIM];            // tf32-rounded attention out
__device__ float g_Wt[4 * DIM * DIM];                 // W^T, tf32-rounded

// ---------------------------------------------------------------------------
__device__ __forceinline__ unsigned smem_u32(const void* p) {
    unsigned a;
    asm("{ .reg .u64 t; cvta.to.shared.u64 t, %1; cvt.u32.u64 %0, t; }"
        : "=r"(a) : "l"(p));
    return a;
}
__device__ __forceinline__ unsigned f2tf32(float f) {
    unsigned u;
    asm("cvt.rna.tf32.f32 %0, %1;" : "=r"(u) : "f"(f));
    return u;
}
__device__ __forceinline__ float uif(unsigned u) { return __uint_as_float(u); }

__device__ __forceinline__ void mma_tf32(float* c, const unsigned* a, const unsigned* b) {
    asm volatile(
        "mma.sync.aligned.m16n8k8.row.col.f32.tf32.tf32.f32 "
        "{%0,%1,%2,%3}, {%4,%5,%6,%7}, {%8,%9}, {%0,%1,%2,%3};"
        : "+f"(c[0]), "+f"(c[1]), "+f"(c[2]), "+f"(c[3])
        : "r"(a[0]), "r"(a[1]), "r"(a[2]), "r"(a[3]), "r"(b[0]), "r"(b[1]));
}
__device__ __forceinline__ void ldsm4(unsigned* r, unsigned addr) {
    asm volatile("ldmatrix.sync.aligned.m8n8.x4.shared.b16 {%0,%1,%2,%3}, [%4];"
        : "=r"(r[0]), "=r"(r[1]), "=r"(r[2]), "=r"(r[3]) : "r"(addr));
}

// ---------------------------------------------------------------------------
// Prepass: round q,k,v inputs to tf32 into g_Xr (A side of GEMMs is pre-rounded)
// ---------------------------------------------------------------------------
__global__ __launch_bounds__(256) void round_inputs(
    const float* __restrict__ q, const float* __restrict__ k,
    const float* __restrict__ v, float* __restrict__ out)
{
    const int z = blockIdx.y;
    const float* src = (z == 0) ? q : (z == 1) ? k : v;
    size_t i = ((size_t)blockIdx.x * 256 + threadIdx.x) * 4;
    float4 a = *(const float4*)(src + i);
    a.x = uif(f2tf32(a.x)); a.y = uif(f2tf32(a.y));
    a.z = uif(f2tf32(a.z)); a.w = uif(f2tf32(a.w));
    *(float4*)(out + (size_t)z * (BATCH * SEQ_L * DIM) + i) = a;
}

// ---------------------------------------------------------------------------
// Batched transpose + tf32 pre-round: g_Wt[z] = round_tf32(W_z^T)
// ---------------------------------------------------------------------------
__global__ __launch_bounds__(256) void transpose4(
    const float* __restrict__ w0, const float* __restrict__ w1,
    const float* __restrict__ w2, const float* __restrict__ w3,
    float* __restrict__ out)
{
    __shared__ float tile[32][33];
    const float* in = (blockIdx.z == 0) ? w0 : (blockIdx.z == 1) ? w1
                    : (blockIdx.z == 2) ? w2 : w3;
    float* o = out + (size_t)blockIdx.z * DIM * DIM;
    const int x = blockIdx.x * 32;
    const int y = blockIdx.y * 32;
    const int tx = threadIdx.x, ty = threadIdx.y;
#pragma unroll
    for (int i = 0; i < 32; i += 8)
        tile[ty + i][tx] = in[(size_t)(y + ty + i) * DIM + x + tx];
    __syncthreads();
#pragma unroll
    for (int i = 0; i < 32; i += 8)
        o[(size_t)(x + ty + i) * DIM + y + tx] = uif(f2tf32(tile[tx][ty + i]));
}

// ---------------------------------------------------------------------------
// tf32 mma.sync GEMM (A and B both pre-rounded -> no cvt; all fragments via
// ldmatrix.x4). CTA 128x128, BK=32, 128 threads = 4 warps of 64x64 tiles.
// grid.z selects per-slice args (QKV fused in one launch).
// remap: 0 row-major; 1 [B,H,L,DH]; 2 [B,H,DH,L] rounded; 3 hi/lo split
// ---------------------------------------------------------------------------
#define BK 32
#define GSMEM (2 * 2 * 128 * 36 * 4)   // 73728 bytes

struct GemmArgs {
    const float* X[3];
    const float* Wt[3];
    const float* bias[3];
    float* out[3];
    float* out2[3];
    int remap[3];
};

__global__ __launch_bounds__(128) void gemm_mma(GemmArgs ga)
{
    extern __shared__ float gsm[];
    const int z = blockIdx.z;
    const float* __restrict__ X = ga.X[z];
    const float* __restrict__ Wt = ga.Wt[z];
    const float* __restrict__ bias = ga.bias[z];
    float* __restrict__ out = ga.out[z];
    float* __restrict__ out2 = ga.out2[z];
    const int remap = ga.remap[z];

    const int tid = threadIdx.x;
    const int wid = tid >> 5, lid = tid & 31;
    const int wm = wid >> 1;
    const int wn = wid & 1;
    const int g = lid >> 2;
    const int t = lid & 3;
    const int bm = blockIdx.y * 128;
    const int bn = blockIdx.x * 128;

    const unsigned uA = smem_u32(gsm);
    const unsigned uB = uA + 36864u;          // Bs after As[2][128][36]

    // ldmatrix per-thread address bases
    const int mi = lid >> 3, ri = lid & 7;
    const unsigned aoff0 = ((unsigned)((wm * 64 + ((mi & 1) << 3) + ri) * 36
                                       + ((mi >> 1) << 2))) << 2;
    const unsigned boff0 = ((unsigned)((wn * 64 + ((mi >> 1) << 3) + ri) * 36
                                       + ((mi & 1) << 2))) << 2;

    float acc[4][8][4];
#pragma unroll
    for (int mf = 0; mf < 4; mf++)
#pragma unroll
        for (int nf = 0; nf < 8; nf++)
#pragma unroll
            for (int r = 0; r < 4; r++) acc[mf][nf][r] = 0.f;

    const int nchunk = DIM / BK;   // 32

#define STAGE(buf_, k0_) do {                                                 \
    _Pragma("unroll")                                                         \
    for (int i_ = 0; i_ < 8; i_++) {                                          \
        int idx = tid + i_ * 128;                                             \
        int row = idx >> 3;                                                   \
        int c4 = (idx & 7) << 2;                                              \
        unsigned da = uA + (((buf_) * 4608 + row * 36 + c4) << 2);            \
        unsigned db = uB + (((buf_) * 4608 + row * 36 + c4) << 2);            \
        const float* sa = X + (size_t)(bm + row) * DIM + (k0_) + c4;          \
        const float* sb = Wt + (size_t)(bn + row) * DIM + (k0_) + c4;         \
        asm volatile("cp.async.ca.shared.global [%0], [%1], 16;" :: "r"(da), "l"(sa)); \
        asm volatile("cp.async.ca.shared.global [%0], [%1], 16;" :: "r"(db), "l"(sb)); \
    }                                                                         \
    asm volatile("cp.async.commit_group;");                                   \
} while (0)

    STAGE(0, 0);

    for (int c = 0; c < nchunk; c++) {
        const int buf = c & 1;
        if (c + 1 < nchunk) {
            STAGE(buf ^ 1, (c + 1) * BK);
            asm volatile("cp.async.wait_group 1;");
        } else {
            asm volatile("cp.async.wait_group 0;");
        }
        __syncthreads();

        const unsigned bufoff = (unsigned)buf * 18432u;
#pragma unroll
        for (int ks = 0; ks < BK; ks += 8) {
            unsigned af[4][4];
#pragma unroll
            for (int mf = 0; mf < 4; mf++)
                ldsm4(af[mf], uA + bufoff + aoff0 + ((mf * 576 + ks) << 2));
#pragma unroll
            for (int p = 0; p < 4; p++) {
                unsigned bb[4];
                ldsm4(bb, uB + bufoff + boff0 + ((p * 576 + ks) << 2));
#pragma unroll
                for (int mf = 0; mf < 4; mf++) {
                    mma_tf32(acc[mf][2 * p], af[mf], &bb[0]);
                    mma_tf32(acc[mf][2 * p + 1], af[mf], &bb[2]);
                }
            }
        }
        __syncthreads();
    }

    // ---- epilogue ----
#pragma unroll
    for (int mf = 0; mf < 4; mf++) {
#pragma unroll
        for (int nf = 0; nf < 8; nf++) {
            int row0 = bm + wm * 64 + mf * 16 + g;
            int col = bn + wn * 64 + nf * 8 + 2 * t;
            float b0 = bias[col], b1 = bias[col + 1];
            float2 vtop = make_float2(acc[mf][nf][0] + b0, acc[mf][nf][1] + b1);
            float2 vbot = make_float2(acc[mf][nf][2] + b0, acc[mf][nf][3] + b1);
            if (remap == 0) {
                *(float2*)&out[(size_t)row0 * DIM + col] = vtop;
                *(float2*)&out[(size_t)(row0 + 8) * DIM + col] = vbot;
            } else {
                int h = col >> 6;
                int dh = col & 63;
#pragma unroll
                for (int rr = 0; rr < 2; rr++) {
                    int row = row0 + rr * 8;
                    int b = row >> 11;
                    int l = row & (SEQ_L - 1);
                    float2 v = rr ? vbot : vtop;
                    if (remap == 1) {
                        size_t idx = ((((size_t)b * NHEAD + h) * SEQ_L + l) << 6) + dh;
                        *(float2*)&out[idx] = v;
                    } else if (remap == 2) {
                        size_t base = (((size_t)b * NHEAD + h) * DHEAD + dh) * SEQ_L + l;
                        out[base] = uif(f2tf32(v.x));
                        out[base + SEQ_L] = uif(f2tf32(v.y));
                    } else {   // remap == 3: hi/lo tf32 split
                        size_t idx = ((((size_t)b * NHEAD + h) * SEQ_L + l) << 6) + dh;
                        float h0 = uif(f2tf32(v.x)), h1 = uif(f2tf32(v.y));
                        *(float2*)&out[idx] = make_float2(h0, h1);
                        *(float2*)&out2[idx] =
                            make_float2(uif(f2tf32(v.x - h0)), uif(f2tf32(v.y - h1)));
                    }
                }
            }
        }
    }
}

// ---------------------------------------------------------------------------
// Tensor-core causal flash attention (tf32 mma.sync), pre-split K, ldmatrix
// fragment loads. Grid (L/128, H, B), 256 threads = 8 warps x 16 q-rows.
// smem: 2 bufs x (Khi 16KB | Klo 16KB | V 16KB) = 98304 B.
// ---------------------------------------------------------------------------
#define LOG2E_SCALE 0.1803368801111204f   // 0.125 * log2(e)

__global__ __launch_bounds__(256, 2) void attn_tc(
    const float* __restrict__ Q, const float* __restrict__ Khi,
    const float* __restrict__ Klo, const float* __restrict__ Vt,
    float* __restrict__ O)
{
    extern __shared__ float sb[];   // [buf][ Khi:4096 | Klo:4096 | V:4096 ] floats
    const unsigned usb = smem_u32(sb);

    const int qb = (gridDim.x - 1) - blockIdx.x;   // heavy CTAs first
    const int h = blockIdx.y;
    const int b = blockIdx.z;
    const int tid = threadIdx.x;
    const int w = tid >> 5, lid = tid & 31;
    const int g = lid >> 2, t = lid & 3;
    const int rowbase = qb * 128 + w * 16;

    const size_t qkOff = (size_t)(b * NHEAD + h) * SEQ_L * DHEAD;
    const size_t vtOff = (size_t)(b * NHEAD + h) * DHEAD * SEQ_L;

    // ldmatrix per-thread constants for B-fragment tiles (swizzled 64x64)
    const int mi = lid >> 3, ri = lid & 7;
    const unsigned jbit = (unsigned)(mi & 1);
    const unsigned frow = ((unsigned)((((mi >> 1) << 3) + ri)) << 8);   // row*64*4 bytes

    // Q rows (rowbase+g, rowbase+g+8), cols ≡ t (mod 4), prescaled
    float qf0[16], qf1[16];
    {
        const float* Qr0 = Q + qkOff + (size_t)(rowbase + g) * DHEAD + t;
        const float* Qr1 = Qr0 + 8 * DHEAD;
#pragma unroll
        for (int i = 0; i < 16; i++) {
            qf0[i] = Qr0[4 * i] * LOG2E_SCALE;
            qf1[i] = Qr1[4 * i] * LOG2E_SCALE;
        }
    }

    float oacc[8][4];
#pragma unroll
    for (int nf = 0; nf < 8; nf++)
#pragma unroll
        for (int r = 0; r < 4; r++) oacc[nf][r] = 0.f;
    float m0 = -1e30f, m1 = -1e30f, l0 = 0.f, l1 = 0.f;

    const int nkb = 2 * qb + 2;

#define LOAD_BLOCK(kb_, buf_) do {                                            \
    float* dKh = sb + (buf_) * 12288;                                         \
    float* dKl = dKh + 4096;                                                  \
    float* dV = dKh + 8192;                                                   \
    const float* gKh = Khi + qkOff + (size_t)((kb_) * 64) * 64;               \
    const float* gKl = Klo + qkOff + (size_t)((kb_) * 64) * 64;               \
    const float* gV = Vt + vtOff + (kb_) * 64;                                \
    _Pragma("unroll")                                                         \
    for (int r_ = 0; r_ < 4; r_++) {                                          \
        int idx = tid + r_ * 256;                                             \
        int row = idx >> 4;                                                   \
        int c4 = (idx & 15) << 2;                                             \
        int sw = (row << 6) + (c4 ^ ((row & 7) << 2));                        \
        unsigned dh_ = smem_u32(dKh + sw);                                    \
        const float* skh = gKh + row * 64 + c4;                               \
        asm volatile("cp.async.ca.shared.global [%0], [%1], 16;" :: "r"(dh_), "l"(skh)); \
        unsigned dl_ = smem_u32(dKl + sw);                                    \
        const float* skl = gKl + row * 64 + c4;                               \
        asm volatile("cp.async.ca.shared.global [%0], [%1], 16;" :: "r"(dl_), "l"(skl)); \
        unsigned dv_ = smem_u32(dV + sw);                                     \
        const float* sv = gV + (size_t)row * SEQ_L + c4;                      \
        asm volatile("cp.async.ca.shared.global [%0], [%1], 16;" :: "r"(dv_), "l"(sv)); \
    }                                                                         \
    asm volatile("cp.async.commit_group;");                                   \
} while (0)

    LOAD_BLOCK(0, 0);

    for (int kb = 0; kb < nkb; kb++) {
        const int buf = kb & 1;
        if (kb + 1 < nkb) {
            LOAD_BLOCK(kb + 1, buf ^ 1);
            asm volatile("cp.async.wait_group 1;");
        } else {
            asm volatile("cp.async.wait_group 0;");
        }
        __syncthreads();

        const int kv0 = kb * 64;
        const bool active = (kv0 <= rowbase + 15);
        if (active) {
            const unsigned uKh = usb + (unsigned)buf * 49152u;
            const unsigned uKl = uKh + 16384u;
            const unsigned uV = uKh + 32768u;

            // ---- S = Q K^T (3-pass tf32 split; K pre-split in gmem) ----
            float sacc[8][4];
#pragma unroll
            for (int nf = 0; nf < 8; nf++)
#pragma unroll
                for (int r = 0; r < 4; r++) sacc[nf][r] = 0.f;

#pragma unroll
            for (int ks = 0; ks < 8; ks++) {
                unsigned qh[4], ql[4];
                qh[0] = f2tf32(qf0[2*ks]);     ql[0] = f2tf32(qf0[2*ks]     - uif(qh[0]));
                qh[1] = f2tf32(qf1[2*ks]);     ql[1] = f2tf32(qf1[2*ks]     - uif(qh[1]));
                qh[2] = f2tf32(qf0[2*ks + 1]); ql[2] = f2tf32(qf0[2*ks + 1] - uif(qh[2]));
                qh[3] = f2tf32(qf1[2*ks + 1]); ql[3] = f2tf32(qf1[2*ks + 1] - uif(qh[3]));
                const unsigned coff = ((((unsigned)(ks << 1) + jbit) ^ (unsigned)ri) << 4);
#pragma unroll
                for (int p = 0; p < 4; p++) {
                    const unsigned off = frow + ((unsigned)p << 12) + coff;
                    unsigned kh[4], kl[4];
                    ldsm4(kh, uKh + off);
                    ldsm4(kl, uKl + off);
                    mma_tf32(sacc[2*p],     qh, &kh[0]);
                    mma_tf32(sacc[2*p],     ql, &kh[0]);
                    mma_tf32(sacc[2*p],     qh, &kl[0]);
                    mma_tf32(sacc[2*p + 1], qh, &kh[2]);
                    mma_tf32(sacc[2*p + 1], ql, &kh[2]);
                    mma_tf32(sacc[2*p + 1], qh, &kl[2]);
                }
            }

            // ---- causal mask (only near diagonal) ----
            if (kv0 + 63 > rowbase) {
#pragma unroll
                for (int nf = 0; nf < 8; nf++)
#pragma unroll
                    for (int r = 0; r < 4; r++) {
                        int col = kv0 + nf * 8 + 2 * t + (r & 1);
                        int row = rowbase + g + ((r >> 1) << 3);
                        if (col > row) sacc[nf][r] = -1e30f;
                    }
            }

            // ---- online softmax (log2 domain) ----
            float mx0 = -1e30f, mx1 = -1e30f;
#pragma unroll
            for (int nf = 0; nf < 8; nf++) {
                mx0 = fmaxf(mx0, fmaxf(sacc[nf][0], sacc[nf][1]));
                mx1 = fmaxf(mx1, fmaxf(sacc[nf][2], sacc[nf][3]));
            }
            mx0 = fmaxf(mx0, __shfl_xor_sync(0xffffffffu, mx0, 1));
            mx0 = fmaxf(mx0, __shfl_xor_sync(0xffffffffu, mx0, 2));
            mx1 = fmaxf(mx1, __shfl_xor_sync(0xffffffffu, mx1, 1));
            mx1 = fmaxf(mx1, __shfl_xor_sync(0xffffffffu, mx1, 2));
            float mn0 = fmaxf(m0, mx0), mn1 = fmaxf(m1, mx1);
            float c0 = exp2f(m0 - mn0), c1 = exp2f(m1 - mn1);
            m0 = mn0; m1 = mn1;

            float s0 = 0.f, s1 = 0.f;
#pragma unroll
            for (int nf = 0; nf < 8; nf++) {
                float p0 = exp2f(sacc[nf][0] - mn0);
                float p1 = exp2f(sacc[nf][1] - mn0);
                float p2 = exp2f(sacc[nf][2] - mn1);
                float p3 = exp2f(sacc[nf][3] - mn1);
                s0 += p0 + p1; s1 += p2 + p3;
                sacc[nf][0] = p0; sacc[nf][1] = p1;
                sacc[nf][2] = p2; sacc[nf][3] = p3;
            }
            s0 += __shfl_xor_sync(0xffffffffu, s0, 1);
            s0 += __shfl_xor_sync(0xffffffffu, s0, 2);
            s1 += __shfl_xor_sync(0xffffffffu, s1, 1);
            s1 += __shfl_xor_sync(0xffffffffu, s1, 2);
            l0 = l0 * c0 + s0;
            l1 = l1 * c1 + s1;
#pragma unroll
            for (int nf = 0; nf < 8; nf++) {
                oacc[nf][0] *= c0; oacc[nf][1] *= c0;
                oacc[nf][2] *= c1; oacc[nf][3] *= c1;
            }

            // ---- O += P V  (P: C-layout -> A-layout via quad shuffles) ----
            const int srcA = (lid & 28) | (t >> 1);
            const int srcB = srcA + 2;
            const bool odd = (t & 1);
#pragma unroll
            for (int f = 0; f < 8; f++) {
                float v0a = __shfl_sync(0xffffffffu, sacc[f][0], srcA);
                float v1a = __shfl_sync(0xffffffffu, sacc[f][1], srcA);
                float v2a = __shfl_sync(0xffffffffu, sacc[f][2], srcA);
                float v3a = __shfl_sync(0xffffffffu, sacc[f][3], srcA);
                float v0b = __shfl_sync(0xffffffffu, sacc[f][0], srcB);
                float v1b = __shfl_sync(0xffffffffu, sacc[f][1], srcB);
                float v2b = __shfl_sync(0xffffffffu, sacc[f][2], srcB);
                float v3b = __shfl_sync(0xffffffffu, sacc[f][3], srcB);
                unsigned pa[4];
                pa[0] = f2tf32(odd ? v1a : v0a);
                pa[1] = f2tf32(odd ? v3a : v2a);
                pa[2] = f2tf32(odd ? v1b : v0b);
                pa[3] = f2tf32(odd ? v3b : v2b);
                const unsigned coff = ((((unsigned)(f << 1) + jbit) ^ (unsigned)ri) << 4);
#pragma unroll
                for (int p = 0; p < 4; p++) {
                    unsigned vv[4];
                    ldsm4(vv, uV + frow + ((unsigned)p << 12) + coff);
                    mma_tf32(oacc[2*p],     pa, &vv[0]);
                    mma_tf32(oacc[2*p + 1], pa, &vv[2]);
                }
            }
        }
        __syncthreads();
    }

    // ---- write O [B, L, D], tf32-rounded (out-proj A side) ----
    float inv0 = 1.f / l0, inv1 = 1.f / l1;
    int row0 = rowbase + g;
    float* O0 = O + ((size_t)b * SEQ_L + row0) * DIM + h * DHEAD;
    float* O1 = O0 + (size_t)8 * DIM;
#pragma unroll
    for (int nf = 0; nf < 8; nf++) {
        int col = nf * 8 + 2 * t;
        *(float2*)&O0[col] = make_float2(uif(f2tf32(oacc[nf][0] * inv0)),
                                         uif(f2tf32(oacc[nf][1] * inv0)));
        *(float2*)&O1[col] = make_float2(uif(f2tf32(oacc[nf][2] * inv1)),
                                         uif(f2tf32(oacc[nf][3] * inv1)));
    }
}

// ---------------------------------------------------------------------------
extern "C" void kernel_launch(void* const* d_in, const int* in_sizes, int n_in,
                              void* d_out, int out_size)
{
    const float* q  = (const float*)d_in[0];
    const float* k  = (const float*)d_in[1];
    const float* v  = (const float*)d_in[2];
    // d_in[3] = mask (causal triu) — applied analytically, not read
    const float* Wq = (const float*)d_in[4];
    const float* bq = (const float*)d_in[5];
    const float* Wk = (const float*)d_in[6];
    const float* bk = (const float*)d_in[7];
    const float* Wv = (const float*)d_in[8];
    const float* bv = (const float*)d_in[9];
    const float* Wo = (const float*)d_in[10];
    const float* bo = (const float*)d_in[11];

    float *gxr, *gq, *gkh, *gkl, *gvt, *go, *gwt;
    cudaGetSymbolAddress((void**)&gxr, g_Xr);
    cudaGetSymbolAddress((void**)&gq, g_Q);
    cudaGetSymbolAddress((void**)&gkh, g_Khi);
    cudaGetSymbolAddress((void**)&gkl, g_Klo);
    cudaGetSymbolAddress((void**)&gvt, g_Vt);
    cudaGetSymbolAddress((void**)&go, g_O);
    cudaGetSymbolAddress((void**)&gwt, g_Wt);

    static int configured = 0;
    if (!configured) {
        cudaFuncSetAttribute(gemm_mma, cudaFuncAttributeMaxDynamicSharedMemorySize, GSMEM);
        cudaFuncSetAttribute(attn_tc, cudaFuncAttributeMaxDynamicSharedMemorySize, 98304);
        configured = 1;
    }

    const int NTOK = BATCH * SEQ_L * DIM;   // 4M floats per tensor

    // Prepass: round inputs; transpose+round weights
    round_inputs<<<dim3(NTOK / 1024, 3), 256>>>(q, k, v, gxr);
    transpose4<<<dim3(32, 32, 4), dim3(32, 8)>>>(Wq, Wk, Wv, Wo, gwt);

    // Fused Q/K/V projection GEMMs (grid.z = 3)
    GemmArgs qkv;
    qkv.X[0] = gxr;            qkv.X[1] = gxr + NTOK;     qkv.X[2] = gxr + 2 * NTOK;
    qkv.Wt[0] = gwt;           qkv.Wt[1] = gwt + DIM*DIM; qkv.Wt[2] = gwt + 2*DIM*DIM;
    qkv.bias[0] = bq;          qkv.bias[1] = bk;          qkv.bias[2] = bv;
    qkv.out[0] = gq;           qkv.out[1] = gkh;          qkv.out[2] = gvt;
    qkv.out2[0] = nullptr;     qkv.out2[1] = gkl;         qkv.out2[2] = nullptr;
    qkv.remap[0] = 1;          qkv.remap[1] = 3;          qkv.remap[2] = 2;
    gemm_mma<<<dim3(DIM / 128, (BATCH * SEQ_L) / 128, 3), 128, GSMEM>>>(qkv);

    attn_tc<<<dim3(SEQ_L / 128, NHEAD, BATCH), 256, 98304>>>(gq, gkh, gkl, gvt, go);

    // Output projection
    GemmArgs op;
    op.X[0] = go;  op.X[1] = nullptr; op.X[2] = nullptr;
    op.Wt[0] = gwt + 3 * DIM * DIM; op.Wt[1] = nullptr; op.Wt[2] = nullptr;
    op.bias[0] = bo; op.bias[1] = nullptr; op.bias[2] = nullptr;
    op.out[0] = (float*)d_out; op.out[1] = nullptr; op.out[2] = nullptr;
    op.out2[0] = nullptr; op.out2[1] = nullptr; op.out2[2] = nullptr;
    op.remap[0] = 0; op.remap[1] = 0; op.remap[2] = 0;
    gemm_mma<<<dim3(DIM / 128, (BATCH * SEQ_L) / 128, 1), 128, GSMEM>>>(op);
}

// round 12
// speedup vs baseline: 6.9949x; 1.1073x over previous
#include <cuda_runtime.h>
#include <cuda_bf16.h>
#include <cstdint>

#define SEQ_L 2048
#define DIM 1024
#define NHEAD 16
#define DHEAD 64
#define BATCH 2

// Scratch (allocation-free)
__device__ float g_Xr[3 * BATCH * SEQ_L * DIM];        // tf32-rounded q,k,v inputs
__device__ float g_Q[BATCH * NHEAD * SEQ_L * DHEAD];
__device__ __nv_bfloat16 g_Kh16[BATCH * NHEAD * SEQ_L * DHEAD];  // K hi (bf16)
__device__ __nv_bfloat16 g_Kl16[BATCH * NHEAD * SEQ_L * DHEAD];  // K lo (bf16)
__device__ float g_Vt[BATCH * NHEAD * DHEAD * SEQ_L]; // V^T [B,H,DH,L], tf32-rounded
__device__ float g_O[BATCH * SEQ_L * DIM];            // tf32-rounded attention out
__device__ float g_Wt[4 * DIM * DIM];                 // W^T, tf32-rounded

// ---------------------------------------------------------------------------
__device__ __forceinline__ unsigned smem_u32(const void* p) {
    unsigned a;
    asm("{ .reg .u64 t; cvta.to.shared.u64 t, %1; cvt.u32.u64 %0, t; }"
        : "=r"(a) : "l"(p));
    return a;
}
__device__ __forceinline__ unsigned f2tf32(float f) {
    unsigned u;
    asm("cvt.rna.tf32.f32 %0, %1;" : "=r"(u) : "f"(f));
    return u;
}
__device__ __forceinline__ float uif(unsigned u) { return __uint_as_float(u); }

__device__ __forceinline__ void mma_tf32(float* c, const unsigned* a, const unsigned* b) {
    asm volatile(
        "mma.sync.aligned.m16n8k8.row.col.f32.tf32.tf32.f32 "
        "{%0,%1,%2,%3}, {%4,%5,%6,%7}, {%8,%9}, {%0,%1,%2,%3};"
        : "+f"(c[0]), "+f"(c[1]), "+f"(c[2]), "+f"(c[3])
        : "r"(a[0]), "r"(a[1]), "r"(a[2]), "r"(a[3]), "r"(b[0]), "r"(b[1]));
}
__device__ __forceinline__ void mma_bf16(float* c, const unsigned* a, unsigned b) {
    asm volatile(
        "mma.sync.aligned.m16n8k8.row.col.f32.bf16.bf16.f32 "
        "{%0,%1,%2,%3}, {%4,%5}, {%6}, {%0,%1,%2,%3};"
        : "+f"(c[0]), "+f"(c[1]), "+f"(c[2]), "+f"(c[3])
        : "r"(a[0]), "r"(a[1]), "r"(b));
}
__device__ __forceinline__ void ldsm4(unsigned* r, unsigned addr) {
    asm volatile("ldmatrix.sync.aligned.m8n8.x4.shared.b16 {%0,%1,%2,%3}, [%4];"
        : "=r"(r[0]), "=r"(r[1]), "=r"(r[2]), "=r"(r[3]) : "r"(addr));
}

// ---------------------------------------------------------------------------
// Prepass: round q,k,v inputs to tf32 into g_Xr
// ---------------------------------------------------------------------------
__global__ __launch_bounds__(256) void round_inputs(
    const float* __restrict__ q, const float* __restrict__ k,
    const float* __restrict__ v, float* __restrict__ out)
{
    const int z = blockIdx.y;
    const float* src = (z == 0) ? q : (z == 1) ? k : v;
    size_t i = ((size_t)blockIdx.x * 256 + threadIdx.x) * 4;
    float4 a = *(const float4*)(src + i);
    a.x = uif(f2tf32(a.x)); a.y = uif(f2tf32(a.y));
    a.z = uif(f2tf32(a.z)); a.w = uif(f2tf32(a.w));
    *(float4*)(out + (size_t)z * (BATCH * SEQ_L * DIM) + i) = a;
}

// ---------------------------------------------------------------------------
// Batched transpose + tf32 pre-round: g_Wt[z] = round_tf32(W_z^T)
// ---------------------------------------------------------------------------
__global__ __launch_bounds__(256) void transpose4(
    const float* __restrict__ w0, const float* __restrict__ w1,
    const float* __restrict__ w2, const float* __restrict__ w3,
    float* __restrict__ out)
{
    __shared__ float tile[32][33];
    const float* in = (blockIdx.z == 0) ? w0 : (blockIdx.z == 1) ? w1
                    : (blockIdx.z == 2) ? w2 : w3;
    float* o = out + (size_t)blockIdx.z * DIM * DIM;
    const int x = blockIdx.x * 32;
    const int y = blockIdx.y * 32;
    const int tx = threadIdx.x, ty = threadIdx.y;
#pragma unroll
    for (int i = 0; i < 32; i += 8)
        tile[ty + i][tx] = in[(size_t)(y + ty + i) * DIM + x + tx];
    __syncthreads();
#pragma unroll
    for (int i = 0; i < 32; i += 8)
        o[(size_t)(x + ty + i) * DIM + y + tx] = uif(f2tf32(tile[tx][ty + i]));
}

// ---------------------------------------------------------------------------
// tf32 mma.sync GEMM, ldmatrix fragments, pre-rounded A and B.
// CTA 128x128, BK=32, 256 threads = 8 warps of 64x32 tiles.
// remap: 0 row-major; 1 [B,H,L,DH]; 2 [B,H,DH,L] rounded; 3 bf16 hi/lo K
// ---------------------------------------------------------------------------
#define BK 32
#define GSMEM (2 * 2 * 128 * 36 * 4)   // 73728 bytes

struct GemmArgs {
    const float* X[3];
    const float* Wt[3];
    const float* bias[3];
    float* out[3];
    float* out2[3];
    int remap[3];
};

__global__ __launch_bounds__(256, 2) void gemm_mma(GemmArgs ga)
{
    extern __shared__ float gsm[];
    const int z = blockIdx.z;
    const float* __restrict__ X = ga.X[z];
    const float* __restrict__ Wt = ga.Wt[z];
    const float* __restrict__ bias = ga.bias[z];
    float* __restrict__ out = ga.out[z];
    float* __restrict__ out2 = ga.out2[z];
    const int remap = ga.remap[z];

    const int tid = threadIdx.x;
    const int wid = tid >> 5, lid = tid & 31;
    const int wm = wid >> 2;        // 0..1 (64-row band)
    const int wn = wid & 3;         // 0..3 (32-col band)
    const int g = lid >> 2;
    const int t = lid & 3;
    const int bm = blockIdx.y * 128;
    const int bn = blockIdx.x * 128;

    const unsigned uA = smem_u32(gsm);
    const unsigned uB = uA + 36864u;

    const int mi = lid >> 3, ri = lid & 7;
    const unsigned aoff0 = ((unsigned)((wm * 64 + ((mi & 1) << 3) + ri) * 36
                                       + ((mi >> 1) << 2))) << 2;
    const unsigned boff0 = ((unsigned)((wn * 32 + ((mi >> 1) << 3) + ri) * 36
                                       + ((mi & 1) << 2))) << 2;

    float acc[4][4][4];
#pragma unroll
    for (int mf = 0; mf < 4; mf++)
#pragma unroll
        for (int nf = 0; nf < 4; nf++)
#pragma unroll
            for (int r = 0; r < 4; r++) acc[mf][nf][r] = 0.f;

    const int nchunk = DIM / BK;   // 32

#define STAGE(buf_, k0_) do {                                                 \
    _Pragma("unroll")                                                         \
    for (int i_ = 0; i_ < 4; i_++) {                                          \
        int idx = tid + i_ * 256;                                             \
        int row = idx >> 3;                                                   \
        int c4 = (idx & 7) << 2;                                              \
        unsigned da = uA + (((buf_) * 4608 + row * 36 + c4) << 2);            \
        unsigned db = uB + (((buf_) * 4608 + row * 36 + c4) << 2);            \
        const float* sa = X + (size_t)(bm + row) * DIM + (k0_) + c4;          \
        const float* sb = Wt + (size_t)(bn + row) * DIM + (k0_) + c4;         \
        asm volatile("cp.async.ca.shared.global [%0], [%1], 16;" :: "r"(da), "l"(sa)); \
        asm volatile("cp.async.ca.shared.global [%0], [%1], 16;" :: "r"(db), "l"(sb)); \
    }                                                                         \
    asm volatile("cp.async.commit_group;");                                   \
} while (0)

    STAGE(0, 0);

    for (int c = 0; c < nchunk; c++) {
        const int buf = c & 1;
        if (c + 1 < nchunk) {
            STAGE(buf ^ 1, (c + 1) * BK);
            asm volatile("cp.async.commit_group;");
            asm volatile("cp.async.wait_group 1;");
        } else {
            asm volatile("cp.async.wait_group 0;");
        }
        __syncthreads();

        const unsigned bufoff = (unsigned)buf * 18432u;
#pragma unroll
        for (int ks = 0; ks < BK; ks += 8) {
            unsigned af[4][4];
#pragma unroll
            for (int mf = 0; mf < 4; mf++)
                ldsm4(af[mf], uA + bufoff + aoff0 + ((mf * 576 + ks) << 2));
#pragma unroll
            for (int p = 0; p < 2; p++) {
                unsigned bb[4];
                ldsm4(bb, uB + bufoff + boff0 + ((p * 576 + ks) << 2));
#pragma unroll
                for (int mf = 0; mf < 4; mf++) {
                    mma_tf32(acc[mf][2 * p], af[mf], &bb[0]);
                    mma_tf32(acc[mf][2 * p + 1], af[mf], &bb[2]);
                }
            }
        }
        __syncthreads();
    }

    // ---- epilogue ----
#pragma unroll
    for (int mf = 0; mf < 4; mf++) {
#pragma unroll
        for (int nf = 0; nf < 4; nf++) {
            int row0 = bm + wm * 64 + mf * 16 + g;
            int col = bn + wn * 32 + nf * 8 + 2 * t;
            float b0 = bias[col], b1 = bias[col + 1];
            float2 vtop = make_float2(acc[mf][nf][0] + b0, acc[mf][nf][1] + b1);
            float2 vbot = make_float2(acc[mf][nf][2] + b0, acc[mf][nf][3] + b1);
            if (remap == 0) {
                *(float2*)&out[(size_t)row0 * DIM + col] = vtop;
                *(float2*)&out[(size_t)(row0 + 8) * DIM + col] = vbot;
            } else {
                int h = col >> 6;
                int dh = col & 63;
#pragma unroll
                for (int rr = 0; rr < 2; rr++) {
                    int row = row0 + rr * 8;
                    int b = row >> 11;
                    int l = row & (SEQ_L - 1);
                    float2 v = rr ? vbot : vtop;
                    if (remap == 1) {
                        size_t idx = ((((size_t)b * NHEAD + h) * SEQ_L + l) << 6) + dh;
                        *(float2*)&out[idx] = v;
                    } else if (remap == 2) {
                        size_t base = (((size_t)b * NHEAD + h) * DHEAD + dh) * SEQ_L + l;
                        out[base] = uif(f2tf32(v.x));
                        out[base + SEQ_L] = uif(f2tf32(v.y));
                    } else {   // remap == 3: bf16 hi/lo split K
                        size_t idx = ((((size_t)b * NHEAD + h) * SEQ_L + l) << 6) + dh;
                        __nv_bfloat162 hp, lp;
                        hp.x = __float2bfloat16(v.x);
                        hp.y = __float2bfloat16(v.y);
                        lp.x = __float2bfloat16(v.x - __bfloat162float(hp.x));
                        lp.y = __float2bfloat16(v.y - __bfloat162float(hp.y));
                        *(__nv_bfloat162*)((__nv_bfloat16*)out + idx) = hp;
                        *(__nv_bfloat162*)((__nv_bfloat16*)out2 + idx) = lp;
                    }
                }
            }
        }
    }
}

// ---------------------------------------------------------------------------
// Tensor-core causal flash attention: bf16 hi/lo 3-pass QK (2x rate),
// tf32 single-pass PV. Grid (L/128, H, B), 256 threads = 8 warps x 16 q-rows.
// smem: 2 bufs x (Khi 8KB bf16 | Klo 8KB bf16 | V 16KB fp32) = 65536 B.
// ---------------------------------------------------------------------------
#define LOG2E_SCALE 0.1803368801111204f   // 0.125 * log2(e)

__global__ __launch_bounds__(256, 2) void attn_tc(
    const float* __restrict__ Q, const __nv_bfloat16* __restrict__ Kh16,
    const __nv_bfloat16* __restrict__ Kl16, const float* __restrict__ Vt,
    float* __restrict__ O)
{
    extern __shared__ float sb[];
    const unsigned usb = smem_u32(sb);

    const int qb = (gridDim.x - 1) - blockIdx.x;   // heavy CTAs first
    const int h = blockIdx.y;
    const int b = blockIdx.z;
    const int tid = threadIdx.x;
    const int w = tid >> 5, lid = tid & 31;
    const int g = lid >> 2, t = lid & 3;
    const int rowbase = qb * 128 + w * 16;

    const size_t qkOff = (size_t)(b * NHEAD + h) * SEQ_L * DHEAD;
    const size_t vtOff = (size_t)(b * NHEAD + h) * DHEAD * SEQ_L;

    // V-tile ldmatrix constants (fp32-as-2xb16 trick, unchanged from R11)
    const int mi = lid >> 3, ri = lid & 7;
    const unsigned jbit = (unsigned)(mi & 1);
    const unsigned frow = ((unsigned)((((mi >> 1) << 3) + ri)) << 8);

    // K-tile ldmatrix base (bf16, 128B rows, 16B-chunk XOR swizzle): n = lid
    const unsigned krow = (unsigned)(lid * 128);
    const unsigned ksw = (unsigned)(lid & 7);

    // ---- Q: load, prescale, bf16 hi/lo split ONCE (A-fragments, k pairs) ----
    unsigned qha[8][2], qla[8][2];
    {
        const float* Qr0 = Q + qkOff + (size_t)(rowbase + g) * DHEAD + 2 * t;
        const float* Qr1 = Qr0 + 8 * DHEAD;
#pragma unroll
        for (int s = 0; s < 8; s++) {
            float x0 = Qr0[8 * s] * LOG2E_SCALE, x1 = Qr0[8 * s + 1] * LOG2E_SCALE;
            float y0 = Qr1[8 * s] * LOG2E_SCALE, y1 = Qr1[8 * s + 1] * LOG2E_SCALE;
            __nv_bfloat162 hx, lx, hy, ly;
            hx.x = __float2bfloat16(x0); hx.y = __float2bfloat16(x1);
            lx.x = __float2bfloat16(x0 - __bfloat162float(hx.x));
            lx.y = __float2bfloat16(x1 - __bfloat162float(hx.y));
            hy.x = __float2bfloat16(y0); hy.y = __float2bfloat16(y1);
            ly.x = __float2bfloat16(y0 - __bfloat162float(hy.x));
            ly.y = __float2bfloat16(y1 - __bfloat162float(hy.y));
            qha[s][0] = *(unsigned*)&hx; qha[s][1] = *(unsigned*)&hy;
            qla[s][0] = *(unsigned*)&lx; qla[s][1] = *(unsigned*)&ly;
        }
    }

    float oacc[8][4];
#pragma unroll
    for (int nf = 0; nf < 8; nf++)
#pragma unroll
        for (int r = 0; r < 4; r++) oacc[nf][r] = 0.f;
    float m0 = -1e30f, m1 = -1e30f, l0 = 0.f, l1 = 0.f;

    const int nkb = 2 * qb + 2;

#define LOAD_BLOCK(kb_, buf_) do {                                            \
    unsigned ub = usb + (buf_) * 32768u;                                      \
    const __nv_bfloat16* gKh = Kh16 + qkOff + (size_t)((kb_) * 64) * 64;      \
    const __nv_bfloat16* gKl = Kl16 + qkOff + (size_t)((kb_) * 64) * 64;      \
    const float* gV = Vt + vtOff + (kb_) * 64;                                \
    _Pragma("unroll")                                                         \
    for (int r_ = 0; r_ < 2; r_++) {                                          \
        int idx = tid + r_ * 256;                                             \
        int row = idx >> 3;                                                   \
        int c = idx & 7;                                                      \
        unsigned sw = ub + (unsigned)(row * 128 + ((c ^ (row & 7)) << 4));    \
        const __nv_bfloat16* skh = gKh + row * 64 + c * 8;                    \
        const __nv_bfloat16* skl = gKl + row * 64 + c * 8;                    \
        asm volatile("cp.async.ca.shared.global [%0], [%1], 16;" :: "r"(sw), "l"(skh)); \
        asm volatile("cp.async.ca.shared.global [%0], [%1], 16;" :: "r"(sw + 8192u), "l"(skl)); \
    }                                                                         \
    _Pragma("unroll")                                                         \
    for (int r_ = 0; r_ < 4; r_++) {                                          \
        int idx = tid + r_ * 256;                                             \
        int row = idx >> 4;                                                   \
        int c4 = (idx & 15) << 2;                                             \
        unsigned sw = ub + 16384u                                             \
            + (unsigned)((((row << 6) + (c4 ^ ((row & 7) << 2)))) << 2);      \
        const float* sv = gV + (size_t)row * SEQ_L + c4;                      \
        asm volatile("cp.async.ca.shared.global [%0], [%1], 16;" :: "r"(sw), "l"(sv)); \
    }                                                                         \
    asm volatile("cp.async.commit_group;");                                   \
} while (0)

    LOAD_BLOCK(0, 0);

    for (int kb = 0; kb < nkb; kb++) {
        const int buf = kb & 1;
        if (kb + 1 < nkb) {
            LOAD_BLOCK(kb + 1, buf ^ 1);
            asm volatile("cp.async.wait_group 1;");
        } else {
            asm volatile("cp.async.wait_group 0;");
        }
        __syncthreads();

        const int kv0 = kb * 64;
        const bool active = (kv0 <= rowbase + 15);
        if (active) {
            const unsigned uKh = usb + (unsigned)buf * 32768u;
            const unsigned uV = uKh + 16384u;

            // ---- S = Q K^T : bf16 hi/lo, 3 mmas per fragment ----
            float sacc[8][4];
#pragma unroll
            for (int nf = 0; nf < 8; nf++)
#pragma unroll
                for (int r = 0; r < 4; r++) sacc[nf][r] = 0.f;

#pragma unroll
            for (int ks = 0; ks < 8; ks++) {
                const unsigned base = uKh + krow + (((unsigned)ks ^ ksw) << 4);
                unsigned kh0[4], kh1[4], kl0[4], kl1[4];
                ldsm4(kh0, base);
                ldsm4(kh1, base + 4096u);
                ldsm4(kl0, base + 8192u);
                ldsm4(kl1, base + 12288u);
#pragma unroll
                for (int j = 0; j < 4; j++) {
                    mma_bf16(sacc[j], qha[ks], kh0[j]);
                    mma_bf16(sacc[j], qla[ks], kh0[j]);
                    mma_bf16(sacc[j], qha[ks], kl0[j]);
                    mma_bf16(sacc[j + 4], qha[ks], kh1[j]);
                    mma_bf16(sacc[j + 4], qla[ks], kh1[j]);
                    mma_bf16(sacc[j + 4], qha[ks], kl1[j]);
                }
            }

            // ---- causal mask (only near diagonal) ----
            if (kv0 + 63 > rowbase) {
#pragma unroll
                for (int nf = 0; nf < 8; nf++)
#pragma unroll
                    for (int r = 0; r < 4; r++) {
                        int col = kv0 + nf * 8 + 2 * t + (r & 1);
                        int row = rowbase + g + ((r >> 1) << 3);
                        if (col > row) sacc[nf][r] = -1e30f;
                    }
            }

            // ---- online softmax (log2 domain) ----
            float mx0 = -1e30f, mx1 = -1e30f;
#pragma unroll
            for (int nf = 0; nf < 8; nf++) {
                mx0 = fmaxf(mx0, fmaxf(sacc[nf][0], sacc[nf][1]));
                mx1 = fmaxf(mx1, fmaxf(sacc[nf][2], sacc[nf][3]));
            }
            mx0 = fmaxf(mx0, __shfl_xor_sync(0xffffffffu, mx0, 1));
            mx0 = fmaxf(mx0, __shfl_xor_sync(0xffffffffu, mx0, 2));
            mx1 = fmaxf(mx1, __shfl_xor_sync(0xffffffffu, mx1, 1));
            mx1 = fmaxf(mx1, __shfl_xor_sync(0xffffffffu, mx1, 2));
            float mn0 = fmaxf(m0, mx0), mn1 = fmaxf(m1, mx1);
            float c0 = exp2f(m0 - mn0), c1 = exp2f(m1 - mn1);
            m0 = mn0; m1 = mn1;

            float s0 = 0.f, s1 = 0.f;
#pragma unroll
            for (int nf = 0; nf < 8; nf++) {
                float p0 = exp2f(sacc[nf][0] - mn0);
                float p1 = exp2f(sacc[nf][1] - mn0);
                float p2 = exp2f(sacc[nf][2] - mn1);
                float p3 = exp2f(sacc[nf][3] - mn1);
                s0 += p0 + p1; s1 += p2 + p3;
                sacc[nf][0] = p0; sacc[nf][1] = p1;
                sacc[nf][2] = p2; sacc[nf][3] = p3;
            }
            s0 += __shfl_xor_sync(0xffffffffu, s0, 1);
            s0 += __shfl_xor_sync(0xffffffffu, s0, 2);
            s1 += __shfl_xor_sync(0xffffffffu, s1, 1);
            s1 += __shfl_xor_sync(0xffffffffu, s1, 2);
            l0 = l0 * c0 + s0;
            l1 = l1 * c1 + s1;
#pragma unroll
            for (int nf = 0; nf < 8; nf++) {
                oacc[nf][0] *= c0; oacc[nf][1] *= c0;
                oacc[nf][2] *= c1; oacc[nf][3] *= c1;
            }

            // ---- O += P V (tf32; P C-layout -> A-layout via quad shuffles) ----
            const int srcA = (lid & 28) | (t >> 1);
            const int srcB = srcA + 2;
            const bool odd = (t & 1);
#pragma unroll
            for (int f = 0; f < 8; f++) {
                float v0a = __shfl_sync(0xffffffffu, sacc[f][0], srcA);
                float v1a = __shfl_sync(0xffffffffu, sacc[f][1], srcA);
                float v2a = __shfl_sync(0xffffffffu, sacc[f][2], srcA);
                float v3a = __shfl_sync(0xffffffffu, sacc[f][3], srcA);
                float v0b = __shfl_sync(0xffffffffu, sacc[f][0], srcB);
                float v1b = __shfl_sync(0xffffffffu, sacc[f][1], srcB);
                float v2b = __shfl_sync(0xffffffffu, sacc[f][2], srcB);
                float v3b = __shfl_sync(0xffffffffu, sacc[f][3], srcB);
                unsigned pa[4];
                pa[0] = f2tf32(odd ? v1a : v0a);
                pa[1] = f2tf32(odd ? v3a : v2a);
                pa[2] = f2tf32(odd ? v1b : v0b);
                pa[3] = f2tf32(odd ? v3b : v2b);
                const unsigned coff = ((((unsigned)(f << 1) + jbit) ^ (unsigned)ri) << 4);
#pragma unroll
                for (int p = 0; p < 4; p++) {
                    unsigned vv[4];
                    ldsm4(vv, uV + frow + ((unsigned)p << 12) + coff);
                    mma_tf32(oacc[2*p],     pa, &vv[0]);
                    mma_tf32(oacc[2*p + 1], pa, &vv[2]);
                }
            }
        }
        __syncthreads();
    }

    // ---- write O [B, L, D], tf32-rounded (out-proj A side) ----
    float inv0 = 1.f / l0, inv1 = 1.f / l1;
    int row0 = rowbase + g;
    float* O0 = O + ((size_t)b * SEQ_L + row0) * DIM + h * DHEAD;
    float* O1 = O0 + (size_t)8 * DIM;
#pragma unroll
    for (int nf = 0; nf < 8; nf++) {
        int col = nf * 8 + 2 * t;
        *(float2*)&O0[col] = make_float2(uif(f2tf32(oacc[nf][0] * inv0)),
                                         uif(f2tf32(oacc[nf][1] * inv0)));
        *(float2*)&O1[col] = make_float2(uif(f2tf32(oacc[nf][2] * inv1)),
                                         uif(f2tf32(oacc[nf][3] * inv1)));
    }
}

// ---------------------------------------------------------------------------
extern "C" void kernel_launch(void* const* d_in, const int* in_sizes, int n_in,
                              void* d_out, int out_size)
{
    const float* q  = (const float*)d_in[0];
    const float* k  = (const float*)d_in[1];
    const float* v  = (const float*)d_in[2];
    // d_in[3] = mask (causal triu) — applied analytically, not read
    const float* Wq = (const float*)d_in[4];
    const float* bq = (const float*)d_in[5];
    const float* Wk = (const float*)d_in[6];
    const float* bk = (const float*)d_in[7];
    const float* Wv = (const float*)d_in[8];
    const float* bv = (const float*)d_in[9];
    const float* Wo = (const float*)d_in[10];
    const float* bo = (const float*)d_in[11];

    float *gxr, *gq, *gvt, *go, *gwt;
    __nv_bfloat16 *gkh, *gkl;
    cudaGetSymbolAddress((void**)&gxr, g_Xr);
    cudaGetSymbolAddress((void**)&gq, g_Q);
    cudaGetSymbolAddress((void**)&gkh, g_Kh16);
    cudaGetSymbolAddress((void**)&gkl, g_Kl16);
    cudaGetSymbolAddress((void**)&gvt, g_Vt);
    cudaGetSymbolAddress((void**)&go, g_O);
    cudaGetSymbolAddress((void**)&gwt, g_Wt);

    static int configured = 0;
    if (!configured) {
        cudaFuncSetAttribute(gemm_mma, cudaFuncAttributeMaxDynamicSharedMemorySize, GSMEM);
        cudaFuncSetAttribute(attn_tc, cudaFuncAttributeMaxDynamicSharedMemorySize, 65536);
        configured = 1;
    }

    const int NTOK = BATCH * SEQ_L * DIM;   // 4M floats per tensor

    round_inputs<<<dim3(NTOK / 1024, 3), 256>>>(q, k, v, gxr);
    transpose4<<<dim3(32, 32, 4), dim3(32, 8)>>>(Wq, Wk, Wv, Wo, gwt);

    // Fused Q/K/V projection GEMMs (grid.z = 3)
    GemmArgs qkv;
    qkv.X[0] = gxr;            qkv.X[1] = gxr + NTOK;     qkv.X[2] = gxr + 2 * NTOK;
    qkv.Wt[0] = gwt;           qkv.Wt[1] = gwt + DIM*DIM; qkv.Wt[2] = gwt + 2*DIM*DIM;
    qkv.bias[0] = bq;          qkv.bias[1] = bk;          qkv.bias[2] = bv;
    qkv.out[0] = gq;           qkv.out[1] = (float*)gkh;  qkv.out[2] = gvt;
    qkv.out2[0] = nullptr;     qkv.out2[1] = (float*)gkl; qkv.out2[2] = nullptr;
    qkv.remap[0] = 1;          qkv.remap[1] = 3;          qkv.remap[2] = 2;
    gemm_mma<<<dim3(DIM / 128, (BATCH * SEQ_L) / 128, 3), 256, GSMEM>>>(qkv);

    attn_tc<<<dim3(SEQ_L / 128, NHEAD, BATCH), 256, 65536>>>(gq, gkh, gkl, gvt, go);

    // Output projection
    GemmArgs op;
    op.X[0] = go;  op.X[1] = nullptr; op.X[2] = nullptr;
    op.Wt[0] = gwt + 3 * DIM * DIM; op.Wt[1] = nullptr; op.Wt[2] = nullptr;
    op.bias[0] = bo; op.bias[1] = nullptr; op.bias[2] = nullptr;
    op.out[0] = (float*)d_out; op.out[1] = nullptr; op.out[2] = nullptr;
    op.out2[0] = nullptr; op.out2[1] = nullptr; op.out2[2] = nullptr;
    op.remap[0] = 0; op.remap[1] = 0; op.remap[2] = 0;
    gemm_mma<<<dim3(DIM / 128, (BATCH * SEQ_L) / 128, 1), 256, GSMEM>>>(op);
}